// round 1
// baseline (speedup 1.0000x reference)
#include <cuda_runtime.h>
#include <math.h>
#include <stdint.h>

#define V_NODES 500000
#define VD 256
#define G_NUM 4000
#define H_HEADS 8
#define GD 256
#define HID 128

#define TM 128          // node rows per CTA tile
#define KB 16           // k-chunk
#define SE_PAD 20       // sE row pitch (keeps float4 alignment: 20 % 4 == 0)
#define CPITCH (HID + 4)  // 132, pitch of sC / sHt

// -------- scratch (no allocations allowed -> __device__ globals) --------
__device__ float g_scores[(size_t)V_NODES * H_HEADS];   // 16 MB
__device__ float g_m[G_NUM * H_HEADS];
__device__ float g_d[G_NUM * H_HEADS];
__device__ int   g_start_arr[G_NUM + 1];

// -------- f32x2 helpers --------
__device__ __forceinline__ void fma2(unsigned long long& d,
                                     unsigned long long a,
                                     unsigned long long b) {
    asm("fma.rn.f32x2 %0, %1, %2, %0;" : "+l"(d) : "l"(a), "l"(b));
}
__device__ __forceinline__ unsigned long long bcast2(float f) {
    unsigned long long r;
    asm("mov.b64 %0, {%1, %1};" : "=l"(r) : "r"(__float_as_uint(f)));
    return r;
}
__device__ __forceinline__ void unpack2(unsigned long long v, float& lo, float& hi) {
    unsigned int l, h;
    asm("mov.b64 {%0, %1}, %2;" : "=r"(l), "=r"(h) : "l"(v));
    lo = __uint_as_float(l);
    hi = __uint_as_float(h);
}

// -------- zero output --------
__global__ void k_zero(float* __restrict__ out, int n) {
    int i = blockIdx.x * blockDim.x + threadIdx.x;
    if (i < n) out[i] = 0.0f;
}

// -------- per-graph start offsets from sorted map --------
__global__ void k_offsets(const int* __restrict__ map) {
    int v = blockIdx.x * blockDim.x + threadIdx.x;
    if (v >= V_NODES) return;
    int m = map[v];
    int prev = (v == 0) ? -1 : map[v - 1];
    for (int g = prev + 1; g <= m; ++g) g_start_arr[g] = v;
    if (v == V_NODES - 1) {
        for (int g = m + 1; g <= G_NUM; ++g) g_start_arr[g] = V_NODES;
    }
}

// -------- scoring MLP: scores[v,h] = relu(E @ W1s) @ W2s --------
// dyn smem: region of TM*CPITCH floats. Phase1 aliases sE (TM*SE_PAD=2560)
// + sW (KB*HID=2048) inside it; after main loop it is reused as sC.
__global__ __launch_bounds__(256)
void k_scores(const float* __restrict__ E,
              const float* __restrict__ W1,
              const float* __restrict__ W2) {
    extern __shared__ float smem[];
    float* sE = smem;                 // 2560 floats
    float* sW = smem + TM * SE_PAD;   // 2048 floats
    float* sC = smem;                 // TM*CPITCH floats (aliased, used after)
    __shared__ float sW2[HID * H_HEADS];

    int tid = threadIdx.x;
    int m0 = blockIdx.x * TM;
    int tx = tid & 15, ty = tid >> 4;

    for (int i = tid; i < HID * H_HEADS; i += 256) sW2[i] = W2[i];

    unsigned long long acc[8][4];
#pragma unroll
    for (int i = 0; i < 8; ++i)
#pragma unroll
        for (int q = 0; q < 4; ++q) acc[i][q] = 0ULL;

    for (int k0 = 0; k0 < VD; k0 += KB) {
        // load E tile [TM x KB]
        {
            int r = tid >> 1;
            int kb = (tid & 1) * 8;
            int v = m0 + r;
            float4 a = make_float4(0.f, 0.f, 0.f, 0.f);
            float4 b = make_float4(0.f, 0.f, 0.f, 0.f);
            if (v < V_NODES) {
                const float* src = E + (size_t)v * VD + k0 + kb;
                a = *(const float4*)src;
                b = *(const float4*)(src + 4);
            }
            *(float4*)&sE[r * SE_PAD + kb]     = a;
            *(float4*)&sE[r * SE_PAD + kb + 4] = b;
        }
        // load W1 tile [KB x HID]
        {
            int kk = tid >> 4;
            int cb = (tid & 15) * 8;
            const float* src = W1 + (size_t)(k0 + kk) * HID + cb;
            *(float4*)&sW[kk * HID + cb]     = *(const float4*)src;
            *(float4*)&sW[kk * HID + cb + 4] = *(const float4*)(src + 4);
        }
        __syncthreads();
#pragma unroll 4
        for (int kk = 0; kk < KB; ++kk) {
            unsigned long long wv[4];
#pragma unroll
            for (int q = 0; q < 4; ++q)
                wv[q] = *(const unsigned long long*)&sW[kk * HID + 2 * tx + 32 * q];
#pragma unroll
            for (int i = 0; i < 8; ++i) {
                unsigned long long e2 = bcast2(sE[(ty * 8 + i) * SE_PAD + kk]);
#pragma unroll
                for (int q = 0; q < 4; ++q) fma2(acc[i][q], e2, wv[q]);
            }
        }
        __syncthreads();
    }

    // relu -> sC
#pragma unroll
    for (int i = 0; i < 8; ++i) {
        int row = ty * 8 + i;
#pragma unroll
        for (int q = 0; q < 4; ++q) {
            float lo, hi;
            unpack2(acc[i][q], lo, hi);
            int c = 2 * tx + 32 * q;
            sC[row * CPITCH + c]     = fmaxf(lo, 0.f);
            sC[row * CPITCH + c + 1] = fmaxf(hi, 0.f);
        }
    }
    __syncthreads();

    // second layer: scores[row, h] = sum_hid sC * W2
#pragma unroll
    for (int rep = 0; rep < 4; ++rep) {
        int o = tid + 256 * rep;           // 0..1023
        int row = o >> 3, h = o & 7;
        int v = m0 + row;
        if (v < V_NODES) {
            float sum = 0.f;
#pragma unroll 8
            for (int hid = 0; hid < HID; ++hid)
                sum += sC[row * CPITCH + hid] * sW2[hid * H_HEADS + h];
            g_scores[(size_t)v * H_HEADS + h] = sum;
        }
    }
}

// -------- per-graph softmax stats (max, sum of exp) --------
__global__ __launch_bounds__(128)
void k_segstats() {
    int g = blockIdx.x;
    int s = g_start_arr[g], e = g_start_arr[g + 1];
    __shared__ float red[128];
    __shared__ float sm8[8];
    int tid = threadIdx.x, h = tid & 7, k = tid >> 3;

    float mx = -INFINITY;
    for (int v = s + k; v < e; v += 16) mx = fmaxf(mx, g_scores[(size_t)v * 8 + h]);
    red[tid] = mx;
    __syncthreads();
    for (int st = 64; st >= 8; st >>= 1) {
        if (tid < st) red[tid] = fmaxf(red[tid], red[tid + st]);
        __syncthreads();
    }
    if (tid < 8) {
        float m = red[tid];
        if (!isfinite(m)) m = 0.0f;
        sm8[tid] = m;
        g_m[g * 8 + tid] = m;
    }
    __syncthreads();

    float m = sm8[h];
    float sum = 0.f;
    for (int v = s + k; v < e; v += 16) sum += expf(g_scores[(size_t)v * 8 + h] - m);
    red[tid] = sum;
    __syncthreads();
    for (int st = 64; st >= 8; st >>= 1) {
        if (tid < st) red[tid] += red[tid + st];
        __syncthreads();
    }
    if (tid < 8) g_d[g * 8 + tid] = red[tid];
}

// -------- transform MLP + softmax weighting + segment sum --------
// dyn smem layout (floats):
//   [0, 16896)            sHt (TM x CPITCH); phase1 aliases sE+sW inside
//   [16896, 25600)        sB : W2t chunk (128x64=8192) then reused as sR (128x68=8704)
//   [25600, 26624)        swgt (TM x 8)
__global__ __launch_bounds__(256)
void k_transform(const float* __restrict__ E,
                 const int* __restrict__ map,
                 const float* __restrict__ W1,
                 const float* __restrict__ W2,
                 float* __restrict__ out) {
    extern __shared__ float smem[];
    float* sE   = smem;
    float* sW   = smem + TM * SE_PAD;
    float* sHt  = smem;
    float* sB   = smem + TM * CPITCH;           // 8704 floats
    float* swgt = smem + TM * CPITCH + 8704;    // 1024 floats
    __shared__ int smap[TM];
    __shared__ int segStart[TM + 1];
    __shared__ int segGraph[TM];
    __shared__ int nseg;

    int tid = threadIdx.x;
    int m0 = blockIdx.x * TM;
    int tx = tid & 15, ty = tid >> 4;

    // softmax weights + map for this tile (independent of the GEMM)
#pragma unroll
    for (int rep = 0; rep < 4; ++rep) {
        int o = tid + 256 * rep;
        int row = o >> 3, h = o & 7;
        int v = m0 + row;
        float w = 0.f;
        if (v < V_NODES) {
            int g = map[v];
            if (h == 0) smap[row] = g;
            float D = g_d[g * H_HEADS + h];
            if (D > 0.f)
                w = expf(g_scores[(size_t)v * H_HEADS + h] - g_m[g * H_HEADS + h]) / D;
        } else if (h == 0) {
            smap[row] = -1;
        }
        swgt[o] = w;
    }
    __syncthreads();
    if (tid == 0) {
        int ns = 0, prev = -2;
        int endr = TM;
        for (int r = 0; r < TM; ++r) {
            int mg = smap[r];
            if (mg < 0) { endr = r; break; }
            if (mg != prev) { segStart[ns] = r; segGraph[ns] = mg; prev = mg; ++ns; }
        }
        segStart[ns] = endr;
        nseg = ns;
    }

    // phase 1: Ht = relu(E @ W1t), [TM x HID]
    unsigned long long acc[8][4];
#pragma unroll
    for (int i = 0; i < 8; ++i)
#pragma unroll
        for (int q = 0; q < 4; ++q) acc[i][q] = 0ULL;

    for (int k0 = 0; k0 < VD; k0 += KB) {
        {
            int r = tid >> 1;
            int kb = (tid & 1) * 8;
            int v = m0 + r;
            float4 a = make_float4(0.f, 0.f, 0.f, 0.f);
            float4 b = make_float4(0.f, 0.f, 0.f, 0.f);
            if (v < V_NODES) {
                const float* src = E + (size_t)v * VD + k0 + kb;
                a = *(const float4*)src;
                b = *(const float4*)(src + 4);
            }
            *(float4*)&sE[r * SE_PAD + kb]     = a;
            *(float4*)&sE[r * SE_PAD + kb + 4] = b;
        }
        {
            int kk = tid >> 4;
            int cb = (tid & 15) * 8;
            const float* src = W1 + (size_t)(k0 + kk) * HID + cb;
            *(float4*)&sW[kk * HID + cb]     = *(const float4*)src;
            *(float4*)&sW[kk * HID + cb + 4] = *(const float4*)(src + 4);
        }
        __syncthreads();
#pragma unroll 4
        for (int kk = 0; kk < KB; ++kk) {
            unsigned long long wv[4];
#pragma unroll
            for (int q = 0; q < 4; ++q)
                wv[q] = *(const unsigned long long*)&sW[kk * HID + 2 * tx + 32 * q];
#pragma unroll
            for (int i = 0; i < 8; ++i) {
                unsigned long long e2 = bcast2(sE[(ty * 8 + i) * SE_PAD + kk]);
#pragma unroll
                for (int q = 0; q < 4; ++q) fma2(acc[i][q], e2, wv[q]);
            }
        }
        __syncthreads();
    }

#pragma unroll
    for (int i = 0; i < 8; ++i) {
        int row = ty * 8 + i;
#pragma unroll
        for (int q = 0; q < 4; ++q) {
            float lo, hi;
            unpack2(acc[i][q], lo, hi);
            int c = 2 * tx + 32 * q;
            sHt[row * CPITCH + c]     = fmaxf(lo, 0.f);
            sHt[row * CPITCH + c + 1] = fmaxf(hi, 0.f);
        }
    }
    __syncthreads();

    // phase 2: per 64-col chunk: R = relu(Ht @ W2t_chunk), weight, segment-reduce
    for (int cc = 0; cc < 4; ++cc) {
        int c0 = cc * 64;
        // load W2t chunk [HID x 64] into sB
        {
            int hid = tid >> 1;
            int cb = (tid & 1) * 32;
            const float* src = W2 + (size_t)hid * GD + c0 + cb;
            float* dst = &sB[hid * 64 + cb];
#pragma unroll
            for (int t = 0; t < 8; ++t)
                *(float4*)(dst + t * 4) = *(const float4*)(src + t * 4);
        }
        __syncthreads();

        unsigned long long acc2[8][2];
#pragma unroll
        for (int i = 0; i < 8; ++i) { acc2[i][0] = 0ULL; acc2[i][1] = 0ULL; }

#pragma unroll 4
        for (int hid = 0; hid < HID; ++hid) {
            unsigned long long wv0 = *(const unsigned long long*)&sB[hid * 64 + 2 * tx];
            unsigned long long wv1 = *(const unsigned long long*)&sB[hid * 64 + 2 * tx + 32];
#pragma unroll
            for (int i = 0; i < 8; ++i) {
                unsigned long long h2 = bcast2(sHt[(ty * 8 + i) * CPITCH + hid]);
                fma2(acc2[i][0], h2, wv0);
                fma2(acc2[i][1], h2, wv1);
            }
        }
        __syncthreads();  // done reading sB as W2 chunk

        // relu * weight -> sR (aliases sB), pitch 68
#pragma unroll
        for (int i = 0; i < 8; ++i) {
            int row = ty * 8 + i;
#pragma unroll
            for (int q = 0; q < 2; ++q) {
                int c = 2 * tx + 32 * q;
                int head = cc * 2 + q;   // (c0 + c) >> 5, both lanes same head
                float w = swgt[row * H_HEADS + head];
                float lo, hi;
                unpack2(acc2[i][q], lo, hi);
                sB[row * 68 + c]     = fmaxf(lo, 0.f) * w;
                sB[row * 68 + c + 1] = fmaxf(hi, 0.f) * w;
            }
        }
        __syncthreads();

        // segment-reduce rows, one atomicAdd per (segment, col)
        {
            int col = tid & 63, slot = tid >> 6;
            for (int s = slot; s < nseg; s += 4) {
                int r0 = segStart[s], r1 = segStart[s + 1];
                float sum = 0.f;
                for (int r = r0; r < r1; ++r) sum += sB[r * 68 + col];
                atomicAdd(&out[(size_t)segGraph[s] * GD + c0 + col], sum);
            }
        }
        __syncthreads();
    }
}

// -------- launch --------
extern "C" void kernel_launch(void* const* d_in, const int* in_sizes, int n_in,
                              void* d_out, int out_size) {
    const float* E   = (const float*)d_in[0];
    const int*   map = (const int*)d_in[1];
    // num_graphs may or may not be materialized as an input; detect via size.
    int base = (in_sizes[2] == 1) ? 3 : 2;
    const float* sw1 = (const float*)d_in[base + 0];
    const float* sw2 = (const float*)d_in[base + 1];
    const float* tw1 = (const float*)d_in[base + 2];
    const float* tw2 = (const float*)d_in[base + 3];
    float* out = (float*)d_out;

    const int smem_scores    = TM * CPITCH * 4;                    // 67584 B
    const int smem_transform = (TM * CPITCH + 8704 + 1024) * 4;    // 106496 B
    cudaFuncSetAttribute(k_scores, cudaFuncAttributeMaxDynamicSharedMemorySize,
                         smem_scores);
    cudaFuncSetAttribute(k_transform, cudaFuncAttributeMaxDynamicSharedMemorySize,
                         smem_transform);

    int nOut = G_NUM * GD;
    int nTiles = (V_NODES + TM - 1) / TM;

    k_zero<<<(nOut + 255) / 256, 256>>>(out, nOut);
    k_offsets<<<(V_NODES + 255) / 256, 256>>>(map);
    k_scores<<<nTiles, 256, smem_scores>>>(E, sw1, sw2);
    k_segstats<<<G_NUM, 128>>>();
    k_transform<<<nTiles, 256, smem_transform>>>(E, map, tw1, tw2, out);
}

// round 2
// speedup vs baseline: 1.0012x; 1.0012x over previous
#include <cuda_runtime.h>
#include <math.h>
#include <stdint.h>

#define V_NODES 500000
#define VD 256
#define G_NUM 4000
#define H_HEADS 8
#define GD 256
#define HID 128

#define TM 128          // node rows per CTA tile
#define KB 16           // k-chunk
#define SE_PAD 20       // sE row pitch (keeps float4 alignment: 20 % 4 == 0)
#define CPITCH (HID + 4)  // 132, pitch of sC / sHt

// -------- scratch (no allocations allowed -> __device__ globals) --------
__device__ float g_scores[(size_t)V_NODES * H_HEADS];   // 16 MB
__device__ float g_m[G_NUM * H_HEADS];
__device__ float g_d[G_NUM * H_HEADS];
__device__ int   g_start_arr[G_NUM + 1];

// -------- f32x2 helpers --------
__device__ __forceinline__ void fma2(unsigned long long& d,
                                     unsigned long long a,
                                     unsigned long long b) {
    asm("fma.rn.f32x2 %0, %1, %2, %0;" : "+l"(d) : "l"(a), "l"(b));
}
__device__ __forceinline__ unsigned long long bcast2(float f) {
    unsigned long long r;
    asm("mov.b64 %0, {%1, %1};" : "=l"(r) : "r"(__float_as_uint(f)));
    return r;
}
__device__ __forceinline__ void unpack2(unsigned long long v, float& lo, float& hi) {
    unsigned int l, h;
    asm("mov.b64 {%0, %1}, %2;" : "=r"(l), "=r"(h) : "l"(v));
    lo = __uint_as_float(l);
    hi = __uint_as_float(h);
}

// -------- zero output --------
__global__ void k_zero(float* __restrict__ out, int n) {
    int i = blockIdx.x * blockDim.x + threadIdx.x;
    if (i < n) out[i] = 0.0f;
}

// -------- per-graph start offsets from sorted map --------
__global__ void k_offsets(const int* __restrict__ map) {
    int v = blockIdx.x * blockDim.x + threadIdx.x;
    if (v >= V_NODES) return;
    int m = map[v];
    int prev = (v == 0) ? -1 : map[v - 1];
    for (int g = prev + 1; g <= m; ++g) g_start_arr[g] = v;
    if (v == V_NODES - 1) {
        for (int g = m + 1; g <= G_NUM; ++g) g_start_arr[g] = V_NODES;
    }
}

// -------- scoring MLP: scores[v,h] = relu(E @ W1s) @ W2s --------
// dyn smem: region of TM*CPITCH floats. Phase1 aliases sE (TM*SE_PAD=2560)
// + sW (KB*HID=2048) inside it; after main loop it is reused as sC.
__global__ __launch_bounds__(256)
void k_scores(const float* __restrict__ E,
              const float* __restrict__ W1,
              const float* __restrict__ W2) {
    extern __shared__ float smem[];
    float* sE = smem;                 // 2560 floats
    float* sW = smem + TM * SE_PAD;   // 2048 floats
    float* sC = smem;                 // TM*CPITCH floats (aliased, used after)
    __shared__ float sW2[HID * H_HEADS];

    int tid = threadIdx.x;
    int m0 = blockIdx.x * TM;
    int tx = tid & 15, ty = tid >> 4;

    for (int i = tid; i < HID * H_HEADS; i += 256) sW2[i] = W2[i];

    unsigned long long acc[8][4];
#pragma unroll
    for (int i = 0; i < 8; ++i)
#pragma unroll
        for (int q = 0; q < 4; ++q) acc[i][q] = 0ULL;

    for (int k0 = 0; k0 < VD; k0 += KB) {
        // load E tile [TM x KB]
        {
            int r = tid >> 1;
            int kb = (tid & 1) * 8;
            int v = m0 + r;
            float4 a = make_float4(0.f, 0.f, 0.f, 0.f);
            float4 b = make_float4(0.f, 0.f, 0.f, 0.f);
            if (v < V_NODES) {
                const float* src = E + (size_t)v * VD + k0 + kb;
                a = *(const float4*)src;
                b = *(const float4*)(src + 4);
            }
            *(float4*)&sE[r * SE_PAD + kb]     = a;
            *(float4*)&sE[r * SE_PAD + kb + 4] = b;
        }
        // load W1 tile [KB x HID]
        {
            int kk = tid >> 4;
            int cb = (tid & 15) * 8;
            const float* src = W1 + (size_t)(k0 + kk) * HID + cb;
            *(float4*)&sW[kk * HID + cb]     = *(const float4*)src;
            *(float4*)&sW[kk * HID + cb + 4] = *(const float4*)(src + 4);
        }
        __syncthreads();
#pragma unroll 4
        for (int kk = 0; kk < KB; ++kk) {
            unsigned long long wv[4];
#pragma unroll
            for (int q = 0; q < 4; ++q)
                wv[q] = *(const unsigned long long*)&sW[kk * HID + 2 * tx + 32 * q];
#pragma unroll
            for (int i = 0; i < 8; ++i) {
                unsigned long long e2 = bcast2(sE[(ty * 8 + i) * SE_PAD + kk]);
#pragma unroll
                for (int q = 0; q < 4; ++q) fma2(acc[i][q], e2, wv[q]);
            }
        }
        __syncthreads();
    }

    // relu -> sC
#pragma unroll
    for (int i = 0; i < 8; ++i) {
        int row = ty * 8 + i;
#pragma unroll
        for (int q = 0; q < 4; ++q) {
            float lo, hi;
            unpack2(acc[i][q], lo, hi);
            int c = 2 * tx + 32 * q;
            sC[row * CPITCH + c]     = fmaxf(lo, 0.f);
            sC[row * CPITCH + c + 1] = fmaxf(hi, 0.f);
        }
    }
    __syncthreads();

    // second layer: scores[row, h] = sum_hid sC * W2
#pragma unroll
    for (int rep = 0; rep < 4; ++rep) {
        int o = tid + 256 * rep;           // 0..1023
        int row = o >> 3, h = o & 7;
        int v = m0 + row;
        if (v < V_NODES) {
            float sum = 0.f;
#pragma unroll 8
            for (int hid = 0; hid < HID; ++hid)
                sum += sC[row * CPITCH + hid] * sW2[hid * H_HEADS + h];
            g_scores[(size_t)v * H_HEADS + h] = sum;
        }
    }
}

// -------- per-graph softmax stats (max, sum of exp) --------
__global__ __launch_bounds__(128)
void k_segstats() {
    int g = blockIdx.x;
    int s = g_start_arr[g], e = g_start_arr[g + 1];
    __shared__ float red[128];
    __shared__ float sm8[8];
    int tid = threadIdx.x, h = tid & 7, k = tid >> 3;

    float mx = -INFINITY;
    for (int v = s + k; v < e; v += 16) mx = fmaxf(mx, g_scores[(size_t)v * 8 + h]);
    red[tid] = mx;
    __syncthreads();
    for (int st = 64; st >= 8; st >>= 1) {
        if (tid < st) red[tid] = fmaxf(red[tid], red[tid + st]);
        __syncthreads();
    }
    if (tid < 8) {
        float m = red[tid];
        if (!isfinite(m)) m = 0.0f;
        sm8[tid] = m;
        g_m[g * 8 + tid] = m;
    }
    __syncthreads();

    float m = sm8[h];
    float sum = 0.f;
    for (int v = s + k; v < e; v += 16) sum += expf(g_scores[(size_t)v * 8 + h] - m);
    red[tid] = sum;
    __syncthreads();
    for (int st = 64; st >= 8; st >>= 1) {
        if (tid < st) red[tid] += red[tid + st];
        __syncthreads();
    }
    if (tid < 8) g_d[g * 8 + tid] = red[tid];
}

// -------- transform MLP + softmax weighting + segment sum --------
// dyn smem layout (floats):
//   [0, 16896)            sHt (TM x CPITCH); phase1 aliases sE+sW inside
//   [16896, 25600)        sB : W2t chunk (128x64=8192) then reused as sR (128x68=8704)
//   [25600, 26624)        swgt (TM x 8)
__global__ __launch_bounds__(256)
void k_transform(const float* __restrict__ E,
                 const int* __restrict__ map,
                 const float* __restrict__ W1,
                 const float* __restrict__ W2,
                 float* __restrict__ out) {
    extern __shared__ float smem[];
    float* sE   = smem;
    float* sW   = smem + TM * SE_PAD;
    float* sHt  = smem;
    float* sB   = smem + TM * CPITCH;           // 8704 floats
    float* swgt = smem + TM * CPITCH + 8704;    // 1024 floats
    __shared__ int smap[TM];
    __shared__ int segStart[TM + 1];
    __shared__ int segGraph[TM];
    __shared__ int nseg;

    int tid = threadIdx.x;
    int m0 = blockIdx.x * TM;
    int tx = tid & 15, ty = tid >> 4;

    // softmax weights + map for this tile (independent of the GEMM)
#pragma unroll
    for (int rep = 0; rep < 4; ++rep) {
        int o = tid + 256 * rep;
        int row = o >> 3, h = o & 7;
        int v = m0 + row;
        float w = 0.f;
        if (v < V_NODES) {
            int g = map[v];
            if (h == 0) smap[row] = g;
            float D = g_d[g * H_HEADS + h];
            if (D > 0.f)
                w = expf(g_scores[(size_t)v * H_HEADS + h] - g_m[g * H_HEADS + h]) / D;
        } else if (h == 0) {
            smap[row] = -1;
        }
        swgt[o] = w;
    }
    __syncthreads();
    if (tid == 0) {
        int ns = 0, prev = -2;
        int endr = TM;
        for (int r = 0; r < TM; ++r) {
            int mg = smap[r];
            if (mg < 0) { endr = r; break; }
            if (mg != prev) { segStart[ns] = r; segGraph[ns] = mg; prev = mg; ++ns; }
        }
        segStart[ns] = endr;
        nseg = ns;
    }

    // phase 1: Ht = relu(E @ W1t), [TM x HID]
    unsigned long long acc[8][4];
#pragma unroll
    for (int i = 0; i < 8; ++i)
#pragma unroll
        for (int q = 0; q < 4; ++q) acc[i][q] = 0ULL;

    for (int k0 = 0; k0 < VD; k0 += KB) {
        {
            int r = tid >> 1;
            int kb = (tid & 1) * 8;
            int v = m0 + r;
            float4 a = make_float4(0.f, 0.f, 0.f, 0.f);
            float4 b = make_float4(0.f, 0.f, 0.f, 0.f);
            if (v < V_NODES) {
                const float* src = E + (size_t)v * VD + k0 + kb;
                a = *(const float4*)src;
                b = *(const float4*)(src + 4);
            }
            *(float4*)&sE[r * SE_PAD + kb]     = a;
            *(float4*)&sE[r * SE_PAD + kb + 4] = b;
        }
        {
            int kk = tid >> 4;
            int cb = (tid & 15) * 8;
            const float* src = W1 + (size_t)(k0 + kk) * HID + cb;
            *(float4*)&sW[kk * HID + cb]     = *(const float4*)src;
            *(float4*)&sW[kk * HID + cb + 4] = *(const float4*)(src + 4);
        }
        __syncthreads();
#pragma unroll 4
        for (int kk = 0; kk < KB; ++kk) {
            unsigned long long wv[4];
#pragma unroll
            for (int q = 0; q < 4; ++q)
                wv[q] = *(const unsigned long long*)&sW[kk * HID + 2 * tx + 32 * q];
#pragma unroll
            for (int i = 0; i < 8; ++i) {
                unsigned long long e2 = bcast2(sE[(ty * 8 + i) * SE_PAD + kk]);
#pragma unroll
                for (int q = 0; q < 4; ++q) fma2(acc[i][q], e2, wv[q]);
            }
        }
        __syncthreads();
    }

#pragma unroll
    for (int i = 0; i < 8; ++i) {
        int row = ty * 8 + i;
#pragma unroll
        for (int q = 0; q < 4; ++q) {
            float lo, hi;
            unpack2(acc[i][q], lo, hi);
            int c = 2 * tx + 32 * q;
            sHt[row * CPITCH + c]     = fmaxf(lo, 0.f);
            sHt[row * CPITCH + c + 1] = fmaxf(hi, 0.f);
        }
    }
    __syncthreads();

    // phase 2: per 64-col chunk: R = relu(Ht @ W2t_chunk), weight, segment-reduce
    for (int cc = 0; cc < 4; ++cc) {
        int c0 = cc * 64;
        // load W2t chunk [HID x 64] into sB
        {
            int hid = tid >> 1;
            int cb = (tid & 1) * 32;
            const float* src = W2 + (size_t)hid * GD + c0 + cb;
            float* dst = &sB[hid * 64 + cb];
#pragma unroll
            for (int t = 0; t < 8; ++t)
                *(float4*)(dst + t * 4) = *(const float4*)(src + t * 4);
        }
        __syncthreads();

        unsigned long long acc2[8][2];
#pragma unroll
        for (int i = 0; i < 8; ++i) { acc2[i][0] = 0ULL; acc2[i][1] = 0ULL; }

#pragma unroll 4
        for (int hid = 0; hid < HID; ++hid) {
            unsigned long long wv0 = *(const unsigned long long*)&sB[hid * 64 + 2 * tx];
            unsigned long long wv1 = *(const unsigned long long*)&sB[hid * 64 + 2 * tx + 32];
#pragma unroll
            for (int i = 0; i < 8; ++i) {
                unsigned long long h2 = bcast2(sHt[(ty * 8 + i) * CPITCH + hid]);
                fma2(acc2[i][0], h2, wv0);
                fma2(acc2[i][1], h2, wv1);
            }
        }
        __syncthreads();  // done reading sB as W2 chunk

        // relu * weight -> sR (aliases sB), pitch 68
#pragma unroll
        for (int i = 0; i < 8; ++i) {
            int row = ty * 8 + i;
#pragma unroll
            for (int q = 0; q < 2; ++q) {
                int c = 2 * tx + 32 * q;
                int head = cc * 2 + q;   // (c0 + c) >> 5, both lanes same head
                float w = swgt[row * H_HEADS + head];
                float lo, hi;
                unpack2(acc2[i][q], lo, hi);
                sB[row * 68 + c]     = fmaxf(lo, 0.f) * w;
                sB[row * 68 + c + 1] = fmaxf(hi, 0.f) * w;
            }
        }
        __syncthreads();

        // segment-reduce rows, one atomicAdd per (segment, col)
        {
            int col = tid & 63, slot = tid >> 6;
            for (int s = slot; s < nseg; s += 4) {
                int r0 = segStart[s], r1 = segStart[s + 1];
                float sum = 0.f;
                for (int r = r0; r < r1; ++r) sum += sB[r * 68 + col];
                atomicAdd(&out[(size_t)segGraph[s] * GD + c0 + col], sum);
            }
        }
        __syncthreads();
    }
}

// -------- launch --------
extern "C" void kernel_launch(void* const* d_in, const int* in_sizes, int n_in,
                              void* d_out, int out_size) {
    const float* E   = (const float*)d_in[0];
    const int*   map = (const int*)d_in[1];
    // num_graphs may or may not be materialized as an input; detect via size.
    int base = (in_sizes[2] == 1) ? 3 : 2;
    const float* sw1 = (const float*)d_in[base + 0];
    const float* sw2 = (const float*)d_in[base + 1];
    const float* tw1 = (const float*)d_in[base + 2];
    const float* tw2 = (const float*)d_in[base + 3];
    float* out = (float*)d_out;

    const int smem_scores    = TM * CPITCH * 4;                    // 67584 B
    const int smem_transform = (TM * CPITCH + 8704 + 1024) * 4;    // 106496 B
    cudaFuncSetAttribute(k_scores, cudaFuncAttributeMaxDynamicSharedMemorySize,
                         smem_scores);
    cudaFuncSetAttribute(k_transform, cudaFuncAttributeMaxDynamicSharedMemorySize,
                         smem_transform);

    int nOut = G_NUM * GD;
    int nTiles = (V_NODES + TM - 1) / TM;

    k_zero<<<(nOut + 255) / 256, 256>>>(out, nOut);
    k_offsets<<<(V_NODES + 255) / 256, 256>>>(map);
    k_scores<<<nTiles, 256, smem_scores>>>(E, sw1, sw2);
    k_segstats<<<G_NUM, 128>>>();
    k_transform<<<nTiles, 256, smem_transform>>>(E, map, tw1, tw2, out);
}

// round 4
// speedup vs baseline: 1.1704x; 1.1689x over previous
#include <cuda_runtime.h>
#include <cuda_bf16.h>
#include <math.h>
#include <stdint.h>

#define V_NODES 500000
#define VD 256
#define G_NUM 4000
#define H_HEADS 8
#define GD 256
#define HID 128
#define TM 128

// phase1 smem tile rows: 64 k-values as (hi-pair,lo-pair) u32 pairs = 256B data + 24B pad
#define PG1 35                      // 8-byte granules per row (280B)
#define CHUNK_B1 (128 * PG1)        // granules per 128x64 buffer
// phase2 rows: 128 k-values = 512B data + 24B pad
#define PG2 67                      // 536B
#define CHUNK_B2 (128 * PG2)

// dynamic smem map (bytes)
#define OFF_A(b)  ((b) ? 71680u : 0u)
#define OFF_B(b)  ((b) ? 107520u : 35840u)
#define OFF_A2    143360u
#define OFF_B2(h) ((h) ? 68608u : 0u)
#define SMEM_SCORES 143360
#define SMEM_TRANS  (143360 + 68608)

// -------- device scratch --------
__device__ float g_scores[(size_t)V_NODES * H_HEADS];
__device__ float g_m[G_NUM * H_HEADS];
__device__ float g_d[G_NUM * H_HEADS];
__device__ int   g_start_arr[G_NUM + 1];
// weight images, byte-identical to smem tile layout (incl. pad)
__device__ uint32_t g_b1s[4 * 128 * 70];
__device__ uint32_t g_b1t[4 * 128 * 70];
__device__ uint32_t g_b2t[2 * 128 * 134];

// -------- helpers --------
static __device__ __forceinline__ uint32_t smem_u32(const void* p) {
    uint32_t a;
    asm("{ .reg .u64 t; cvta.to.shared.u64 t, %1; cvt.u32.u64 %0, t; }" : "=r"(a) : "l"(p));
    return a;
}
static __device__ __forceinline__ void lds64(uint32_t& a, uint32_t& b, uint32_t addr) {
    asm volatile("ld.shared.v2.b32 {%0,%1}, [%2];" : "=r"(a), "=r"(b) : "r"(addr));
}
static __device__ __forceinline__ void sts64(uint32_t addr, uint32_t a, uint32_t b) {
    asm volatile("st.shared.v2.b32 [%0], {%1,%2};" :: "r"(addr), "r"(a), "r"(b) : "memory");
}
static __device__ __forceinline__ void cpa8(uint32_t s, const void* g) {
    asm volatile("{ .reg .u64 gp; cvta.to.global.u64 gp, %1; "
                 "cp.async.ca.shared.global [%0], [gp], 8; }"
                 :: "r"(s), "l"(g) : "memory");
}
#define CP_COMMIT() asm volatile("cp.async.commit_group;" ::: "memory")
#define CP_WAIT(n)  asm volatile("cp.async.wait_group %0;" :: "n"(n) : "memory")

static __device__ __forceinline__ void split2(float x0, float x1, uint32_t& h, uint32_t& l) {
    __nv_bfloat16 h0 = __float2bfloat16(x0), h1 = __float2bfloat16(x1);
    float r0 = x0 - __bfloat162float(h0);
    float r1 = x1 - __bfloat162float(h1);
    __nv_bfloat16 l0 = __float2bfloat16(r0), l1 = __float2bfloat16(r1);
    h = (uint32_t)__bfloat16_as_ushort(h0) | ((uint32_t)__bfloat16_as_ushort(h1) << 16);
    l = (uint32_t)__bfloat16_as_ushort(l0) | ((uint32_t)__bfloat16_as_ushort(l1) << 16);
}
static __device__ __forceinline__ void mma16816(float* d, const uint32_t* a,
                                                uint32_t b0, uint32_t b1) {
    asm volatile("mma.sync.aligned.m16n8k16.row.col.f32.bf16.bf16.f32 "
                 "{%0,%1,%2,%3}, {%4,%5,%6,%7}, {%8,%9}, {%0,%1,%2,%3};"
                 : "+f"(d[0]), "+f"(d[1]), "+f"(d[2]), "+f"(d[3])
                 : "r"(a[0]), "r"(a[1]), "r"(a[2]), "r"(a[3]), "r"(b0), "r"(b1));
}

// GEMM over one (A,B) smem buffer pair. acc: [mtile][ntile][4]
template<int PG, int NKS>
static __device__ __forceinline__ void gemm_bufs(uint32_t aB, uint32_t bB,
                                                 float (&acc)[2][8][4],
                                                 int lane, int warpM, int warpN) {
    const int g = lane >> 2, c = lane & 3;
#pragma unroll
    for (int ks = 0; ks < NKS; ++ks) {
        const int j0 = ks * 8 + c;
        uint32_t ah[2][4], al[2][4];
#pragma unroll
        for (int mt = 0; mt < 2; ++mt) {
            int r = warpM * 32 + mt * 16 + g;
            uint32_t base = aB + (uint32_t)(r * PG + j0) * 8u;
            lds64(ah[mt][0], al[mt][0], base);
            lds64(ah[mt][1], al[mt][1], base + (uint32_t)PG * 64u);
            lds64(ah[mt][2], al[mt][2], base + 32u);
            lds64(ah[mt][3], al[mt][3], base + (uint32_t)PG * 64u + 32u);
        }
#pragma unroll
        for (int nt = 0; nt < 8; ++nt) {
            int n = warpN * 64 + nt * 8 + g;
            uint32_t nb = bB + (uint32_t)(n * PG + j0) * 8u;
            uint32_t bh0, bl0, bh1, bl1;
            lds64(bh0, bl0, nb);
            lds64(bh1, bl1, nb + 32u);
#pragma unroll
            for (int mt = 0; mt < 2; ++mt) {
                mma16816(acc[mt][nt], ah[mt], bh0, bh1);
                mma16816(acc[mt][nt], ah[mt], bl0, bl1);
                mma16816(acc[mt][nt], al[mt], bh0, bh1);
            }
        }
    }
}

static __device__ __forceinline__ void ldE(const float* __restrict__ E, int m0, int chunk,
                                           float (&e)[32], int tid) {
    int r = tid >> 1, hh = tid & 1;
    bool ok = (m0 + r) < V_NODES;
    const float4* src = (const float4*)(E + (size_t)(m0 + r) * VD + chunk * 64 + hh * 32);
#pragma unroll
    for (int q = 0; q < 8; ++q) {
        float4 v = ok ? src[q] : make_float4(0.f, 0.f, 0.f, 0.f);
        e[q * 4 + 0] = v.x; e[q * 4 + 1] = v.y;
        e[q * 4 + 2] = v.z; e[q * 4 + 3] = v.w;
    }
}
static __device__ __forceinline__ void stE(uint32_t aB, const float (&e)[32], int tid) {
    int r = tid >> 1, hh = tid & 1;
    uint32_t base = aB + (uint32_t)(r * PG1 + hh * 16) * 8u;
#pragma unroll
    for (int q = 0; q < 16; ++q) {
        uint32_t h, l;
        split2(e[2 * q], e[2 * q + 1], h, l);
        sts64(base + (uint32_t)q * 8u, h, l);
    }
}
static __device__ __forceinline__ void cpB(uint32_t bB, const uint32_t* gsrc,
                                           int tid, int ngran) {
    for (int i = tid; i < ngran; i += 256)
        cpa8(bB + (uint32_t)i * 8u, gsrc + (size_t)i * 2);
}

// phase1: acc += (E tile 128x256) x (W image 256x128), 3xbf16
static __device__ __forceinline__ void phase1(const float* __restrict__ E, int m0,
                                              const uint32_t* __restrict__ bimg,
                                              uint32_t sb, float (&acc)[2][8][4], int tid) {
    int lane = tid & 31, wid = tid >> 5, warpM = wid >> 1, warpN = wid & 1;
    float e[32];
    cpB(sb + OFF_B(0), bimg, tid, CHUNK_B1);
    CP_COMMIT();
    ldE(E, m0, 0, e, tid);
#pragma unroll
    for (int c2 = 0; c2 < 4; ++c2) {
        int b = c2 & 1;
        stE(sb + OFF_A(b), e, tid);
        if (c2 < 3) {
            cpB(sb + OFF_B(b ^ 1), bimg + (size_t)(c2 + 1) * 128 * 70, tid, CHUNK_B1);
            CP_COMMIT();
            CP_WAIT(1);
        } else {
            CP_WAIT(0);
        }
        __syncthreads();
        if (c2 < 3) ldE(E, m0, c2 + 1, e, tid);
        gemm_bufs<PG1, 4>(sb + OFF_A(b), sb + OFF_B(b), acc, lane, warpM, warpN);
        __syncthreads();
    }
}

// -------- trivial kernels --------
__global__ void k_zero(float* __restrict__ out, int n) {
    int i = blockIdx.x * blockDim.x + threadIdx.x;
    if (i < n) out[i] = 0.0f;
}
__global__ void k_offsets(const int* __restrict__ map) {
    int v = blockIdx.x * blockDim.x + threadIdx.x;
    if (v >= V_NODES) return;
    int m = map[v];
    int prev = (v == 0) ? -1 : map[v - 1];
    for (int g = prev + 1; g <= m; ++g) g_start_arr[g] = v;
    if (v == V_NODES - 1)
        for (int g = m + 1; g <= G_NUM; ++g) g_start_arr[g] = V_NODES;
}

// build hi/lo bf16 weight images in smem-mirror layout
__global__ void k_prep(const float* __restrict__ sw1,
                       const float* __restrict__ tw1,
                       const float* __restrict__ tw2) {
    int i = blockIdx.x * blockDim.x + threadIdx.x;
    if (i >= 16384) return;
    {   // W1 images: chunk c, row n, kpair j
        int c = i >> 12, n = (i >> 5) & 127, j = i & 31;
        int k = c * 64 + 2 * j;
        uint32_t h, l;
        int dst = (c * 128 + n) * 70 + 2 * j;
        split2(sw1[(size_t)k * HID + n], sw1[(size_t)(k + 1) * HID + n], h, l);
        g_b1s[dst] = h; g_b1s[dst + 1] = l;
        split2(tw1[(size_t)k * HID + n], tw1[(size_t)(k + 1) * HID + n], h, l);
        g_b1t[dst] = h; g_b1t[dst + 1] = l;
    }
    {   // W2 image: half hf (n block), row n2, kpair j
        int hf = i >> 13, n2 = (i >> 6) & 127, j = i & 63;
        int k = 2 * j, n = hf * 128 + n2;
        uint32_t h, l;
        split2(tw2[(size_t)k * GD + n], tw2[(size_t)(k + 1) * GD + n], h, l);
        int dst = (hf * 128 + n2) * 134 + 2 * j;
        g_b2t[dst] = h; g_b2t[dst + 1] = l;
    }
}

// -------- scoring --------
__global__ void __launch_bounds__(256) k_scores(const float* __restrict__ E,
                                                const float* __restrict__ W2s) {
    extern __shared__ uint8_t smemraw[];
    uint32_t sb = smem_u32(smemraw);
    __shared__ float sW2[HID * 8];
    __shared__ float sScore[TM * 8];
    int tid = threadIdx.x;
    int m0 = blockIdx.x * TM;
    for (int i = tid; i < HID * 8; i += 256) sW2[i] = W2s[i];
    for (int i = tid; i < TM * 8; i += 256) sScore[i] = 0.f;

    float acc[2][8][4];
#pragma unroll
    for (int a = 0; a < 2; ++a)
#pragma unroll
        for (int b = 0; b < 8; ++b)
#pragma unroll
            for (int q = 0; q < 4; ++q) acc[a][b][q] = 0.f;

    phase1(E, m0, g_b1s, sb, acc, tid);

    // second layer (128 -> 8) from fragments
    int lane = tid & 31, wid = tid >> 5, warpM = wid >> 1, warpN = wid & 1;
    int g = lane >> 2, cc = lane & 3;
    float p[4][8];
#pragma unroll
    for (int r = 0; r < 4; ++r)
#pragma unroll
        for (int h = 0; h < 8; ++h) p[r][h] = 0.f;
#pragma unroll
    for (int mt = 0; mt < 2; ++mt)
#pragma unroll
        for (int nt = 0; nt < 8; ++nt) {
            int c0 = warpN * 64 + nt * 8 + cc * 2;
            float v0 = fmaxf(acc[mt][nt][0], 0.f), v1 = fmaxf(acc[mt][nt][1], 0.f);
            float v2 = fmaxf(acc[mt][nt][2], 0.f), v3 = fmaxf(acc[mt][nt][3], 0.f);
#pragma unroll
            for (int h = 0; h < 8; ++h) {
                p[mt * 2 + 0][h] += v0 * sW2[c0 * 8 + h] + v1 * sW2[c0 * 8 + 8 + h];
                p[mt * 2 + 1][h] += v2 * sW2[c0 * 8 + h] + v3 * sW2[c0 * 8 + 8 + h];
            }
        }
#pragma unroll
    for (int off = 1; off <= 2; off <<= 1)
#pragma unroll
        for (int r = 0; r < 4; ++r)
#pragma unroll
            for (int h = 0; h < 8; ++h)
                p[r][h] += __shfl_xor_sync(0xFFFFFFFFu, p[r][h], off);
    if (cc == 0) {
#pragma unroll
        for (int mt = 0; mt < 2; ++mt)
#pragma unroll
            for (int i2 = 0; i2 < 2; ++i2) {
                int row = warpM * 32 + mt * 16 + i2 * 8 + g;
#pragma unroll
                for (int h = 0; h < 8; ++h)
                    atomicAdd(&sScore[row * 8 + h], p[mt * 2 + i2][h]);
            }
    }
    __syncthreads();
    for (int i = tid; i < TM * 8; i += 256) {
        int v = m0 + (i >> 3);
        if (v < V_NODES) g_scores[(size_t)v * 8 + (i & 7)] = sScore[i];
    }
}

// -------- per-graph softmax stats --------
__global__ void __launch_bounds__(128) k_segstats() {
    int g = blockIdx.x;
    int s = g_start_arr[g], e = g_start_arr[g + 1];
    __shared__ float red[128];
    __shared__ float sm8[8];
    int tid = threadIdx.x, h = tid & 7, k = tid >> 3;

    float mx = -INFINITY;
    for (int v = s + k; v < e; v += 16) mx = fmaxf(mx, g_scores[(size_t)v * 8 + h]);
    red[tid] = mx;
    __syncthreads();
    for (int st = 64; st >= 8; st >>= 1) {
        if (tid < st) red[tid] = fmaxf(red[tid], red[tid + st]);
        __syncthreads();
    }
    if (tid < 8) {
        float m = red[tid];
        if (!isfinite(m)) m = 0.0f;
        sm8[tid] = m;
        g_m[g * 8 + tid] = m;
    }
    __syncthreads();
    float m = sm8[h];
    float sum = 0.f;
    for (int v = s + k; v < e; v += 16) sum += expf(g_scores[(size_t)v * 8 + h] - m);
    red[tid] = sum;
    __syncthreads();
    for (int st = 64; st >= 8; st >>= 1) {
        if (tid < st) red[tid] += red[tid + st];
        __syncthreads();
    }
    if (tid < 8) g_d[g * 8 + tid] = red[tid];
}

// -------- transform + weighting + segment sum --------
__global__ void __launch_bounds__(256) k_transform(const float* __restrict__ E,
                                                   const int* __restrict__ map,
                                                   float* __restrict__ out) {
    extern __shared__ uint8_t smemraw[];
    uint32_t sb = smem_u32(smemraw);
    float* sR = (float*)smemraw;   // epilogue staging aliases B2h0 region
    __shared__ float swgt[TM * 8];
    __shared__ int smap[TM];
    __shared__ int segStart[TM + 1];
    __shared__ int segGraph[TM];
    __shared__ int nseg;

    int tid = threadIdx.x;
    int m0 = blockIdx.x * TM;

    // softmax weights + tile->segment structure
    for (int o = tid; o < TM * 8; o += 256) {
        int row = o >> 3, h = o & 7;
        int v = m0 + row;
        float w = 0.f;
        if (v < V_NODES) {
            int gg = map[v];
            if (h == 0) smap[row] = gg;
            float D = g_d[gg * 8 + h];
            if (D > 0.f)
                w = expf(g_scores[(size_t)v * 8 + h] - g_m[gg * 8 + h]) / D;
        } else if (h == 0) {
            smap[row] = -1;
        }
        swgt[o] = w;
    }
    __syncthreads();
    if (tid == 0) {
        int ns = 0, prev = -2, endr = TM;
        for (int r = 0; r < TM; ++r) {
            int mg = smap[r];
            if (mg < 0) { endr = r; break; }
            if (mg != prev) { segStart[ns] = r; segGraph[ns] = mg; prev = mg; ++ns; }
        }
        segStart[ns] = endr;
        nseg = ns;
    }

    float acc[2][8][4];
#pragma unroll
    for (int a = 0; a < 2; ++a)
#pragma unroll
        for (int b = 0; b < 8; ++b)
#pragma unroll
            for (int q = 0; q < 4; ++q) acc[a][b][q] = 0.f;

    phase1(E, m0, g_b1t, sb, acc, tid);

    int lane = tid & 31, wid = tid >> 5, warpM = wid >> 1, warpN = wid & 1;
    int g = lane >> 2, cc = lane & 3;

    // prefetch B2 halves; write A2 = relu(hidden) hi/lo
    cpB(sb + OFF_B2(0), g_b2t, tid, CHUNK_B2);
    CP_COMMIT();
#pragma unroll
    for (int mt = 0; mt < 2; ++mt)
#pragma unroll
        for (int i2 = 0; i2 < 2; ++i2) {
            int row = warpM * 32 + mt * 16 + i2 * 8 + g;
#pragma unroll
            for (int nt = 0; nt < 8; ++nt) {
                int j = warpN * 32 + nt * 4 + cc;
                float x0 = fmaxf(acc[mt][nt][2 * i2], 0.f);
                float x1 = fmaxf(acc[mt][nt][2 * i2 + 1], 0.f);
                uint32_t h, l;
                split2(x0, x1, h, l);
                sts64(sb + OFF_A2 + (uint32_t)(row * PG2 + j) * 8u, h, l);
            }
        }
    cpB(sb + OFF_B2(1), g_b2t + (size_t)128 * 134, tid, CHUNK_B2);
    CP_COMMIT();
    CP_WAIT(1);
    __syncthreads();

#pragma unroll
    for (int half = 0; half < 2; ++half) {
        if (half == 1) {
            CP_WAIT(0);
            __syncthreads();
        }
#pragma unroll
        for (int a = 0; a < 2; ++a)
#pragma unroll
            for (int b = 0; b < 8; ++b)
#pragma unroll
                for (int q = 0; q < 4; ++q) acc[a][b][q] = 0.f;

        gemm_bufs<PG2, 8>(sb + OFF_A2, sb + OFF_B2(half), acc, lane, warpM, warpN);
        __syncthreads();   // everyone done reading B2 bufs before sR overwrite

        // relu * softmax-weight -> sR
#pragma unroll
        for (int mt = 0; mt < 2; ++mt)
#pragma unroll
            for (int i2 = 0; i2 < 2; ++i2) {
                int row = warpM * 32 + mt * 16 + i2 * 8 + g;
#pragma unroll
                for (int nt = 0; nt < 8; ++nt) {
                    int col = warpN * 64 + nt * 8 + cc * 2;
                    int head = half * 4 + warpN * 2 + (nt >> 2);
                    float w = swgt[row * 8 + head];
                    sR[row * 132 + col]     = fmaxf(acc[mt][nt][2 * i2], 0.f) * w;
                    sR[row * 132 + col + 1] = fmaxf(acc[mt][nt][2 * i2 + 1], 0.f) * w;
                }
            }
        __syncthreads();

        // segment-reduce rows, one atomic per (segment, col)
        {
            int col = tid & 127, slot = tid >> 7;
            for (int sg = slot; sg < nseg; sg += 2) {
                int r0 = segStart[sg], r1 = segStart[sg + 1];
                float s = 0.f;
                for (int r = r0; r < r1; ++r) s += sR[r * 132 + col];
                atomicAdd(&out[(size_t)segGraph[sg] * GD + half * 128 + col], s);
            }
        }
        __syncthreads();
    }
}

// -------- launch --------
extern "C" void kernel_launch(void* const* d_in, const int* in_sizes, int n_in,
                              void* d_out, int out_size) {
    const float* E   = (const float*)d_in[0];
    const int*   map = (const int*)d_in[1];
    int base = (in_sizes[2] == 1) ? 3 : 2;
    const float* sw1 = (const float*)d_in[base + 0];
    const float* sw2 = (const float*)d_in[base + 1];
    const float* tw1 = (const float*)d_in[base + 2];
    const float* tw2 = (const float*)d_in[base + 3];
    float* out = (float*)d_out;

    cudaFuncSetAttribute(k_scores, cudaFuncAttributeMaxDynamicSharedMemorySize,
                         SMEM_SCORES);
    cudaFuncSetAttribute(k_transform, cudaFuncAttributeMaxDynamicSharedMemorySize,
                         SMEM_TRANS);

    int nOut = G_NUM * GD;
    int nTiles = (V_NODES + TM - 1) / TM;

    k_zero<<<(nOut + 255) / 256, 256>>>(out, nOut);
    k_offsets<<<(V_NODES + 255) / 256, 256>>>(map);
    k_prep<<<64, 256>>>(sw1, tw1, tw2);
    k_scores<<<nTiles, 256, SMEM_SCORES>>>(E, sw2);
    k_segstats<<<G_NUM, 128>>>();
    k_transform<<<nTiles, 256, SMEM_TRANS>>>(E, map, out);
}

// round 5
// speedup vs baseline: 1.4525x; 1.2411x over previous
#include <cuda_runtime.h>
#include <cuda_bf16.h>
#include <math.h>
#include <stdint.h>

#define V_NODES 500000
#define VD 256
#define G_NUM 4000
#define H_HEADS 8
#define GD 256
#define HID 128
#define TM 128
#define NT 512   // threads per CTA

// phase1 smem tile rows: 64 k-values as (hi-pair,lo-pair) u32 pairs = 256B data + 24B pad
#define PG1 35                      // 8-byte granules per row (280B)
#define CHUNK_B1 (128 * PG1)
// phase2 rows: 128 k-values = 512B data + 24B pad
#define PG2 67                      // 536B
#define CHUNK_B2 (128 * PG2)

// dynamic smem map (bytes)
#define OFF_A(b)  ((b) ? 71680u : 0u)
#define OFF_B(b)  ((b) ? 107520u : 35840u)
#define OFF_A2    143360u
#define OFF_B2(h) ((h) ? 68608u : 0u)
#define SMEM_SCORES 143360
#define SMEM_TRANS  (143360 + 68608)

// -------- device scratch --------
__device__ float g_scores[(size_t)V_NODES * H_HEADS];
__device__ float g_m[G_NUM * H_HEADS];
__device__ float g_d[G_NUM * H_HEADS];
__device__ int   g_start_arr[G_NUM + 1];
__device__ uint32_t g_b1s[4 * 128 * 70];
__device__ uint32_t g_b1t[4 * 128 * 70];
__device__ uint32_t g_b2t[2 * 128 * 134];

// -------- helpers --------
static __device__ __forceinline__ uint32_t smem_u32(const void* p) {
    uint32_t a;
    asm("{ .reg .u64 t; cvta.to.shared.u64 t, %1; cvt.u32.u64 %0, t; }" : "=r"(a) : "l"(p));
    return a;
}
static __device__ __forceinline__ void lds64(uint32_t& a, uint32_t& b, uint32_t addr) {
    asm volatile("ld.shared.v2.b32 {%0,%1}, [%2];" : "=r"(a), "=r"(b) : "r"(addr));
}
static __device__ __forceinline__ void sts64(uint32_t addr, uint32_t a, uint32_t b) {
    asm volatile("st.shared.v2.b32 [%0], {%1,%2};" :: "r"(addr), "r"(a), "r"(b) : "memory");
}
static __device__ __forceinline__ void cpa8(uint32_t s, const void* g) {
    asm volatile("{ .reg .u64 gp; cvta.to.global.u64 gp, %1; "
                 "cp.async.ca.shared.global [%0], [gp], 8; }"
                 :: "r"(s), "l"(g) : "memory");
}
#define CP_COMMIT() asm volatile("cp.async.commit_group;" ::: "memory")
#define CP_WAIT(n)  asm volatile("cp.async.wait_group %0;" :: "n"(n) : "memory")

static __device__ __forceinline__ void split2(float x0, float x1, uint32_t& h, uint32_t& l) {
    __nv_bfloat16 h0 = __float2bfloat16(x0), h1 = __float2bfloat16(x1);
    float r0 = x0 - __bfloat162float(h0);
    float r1 = x1 - __bfloat162float(h1);
    __nv_bfloat16 l0 = __float2bfloat16(r0), l1 = __float2bfloat16(r1);
    h = (uint32_t)__bfloat16_as_ushort(h0) | ((uint32_t)__bfloat16_as_ushort(h1) << 16);
    l = (uint32_t)__bfloat16_as_ushort(l0) | ((uint32_t)__bfloat16_as_ushort(l1) << 16);
}
static __device__ __forceinline__ void mma16816(float* d, const uint32_t* a,
                                                uint32_t b0, uint32_t b1) {
    asm volatile("mma.sync.aligned.m16n8k16.row.col.f32.bf16.bf16.f32 "
                 "{%0,%1,%2,%3}, {%4,%5,%6,%7}, {%8,%9}, {%0,%1,%2,%3};"
                 : "+f"(d[0]), "+f"(d[1]), "+f"(d[2]), "+f"(d[3])
                 : "r"(a[0]), "r"(a[1]), "r"(a[2]), "r"(a[3]), "r"(b0), "r"(b1));
}

// GEMM over one (A,B) smem buffer pair. Warp computes 32x32. acc: [mt][nt][4]
template<int PG, int NKS>
static __device__ __forceinline__ void gemm_bufs(uint32_t aB, uint32_t bB,
                                                 float (&acc)[2][4][4],
                                                 int lane, int warpM, int warpN) {
    const int g = lane >> 2, c = lane & 3;
#pragma unroll
    for (int ks = 0; ks < NKS; ++ks) {
        const int j0 = ks * 8 + c;
        uint32_t ah[2][4], al[2][4];
#pragma unroll
        for (int mt = 0; mt < 2; ++mt) {
            int r = warpM * 32 + mt * 16 + g;
            uint32_t base = aB + (uint32_t)(r * PG + j0) * 8u;
            lds64(ah[mt][0], al[mt][0], base);
            lds64(ah[mt][1], al[mt][1], base + (uint32_t)PG * 64u);
            lds64(ah[mt][2], al[mt][2], base + 32u);
            lds64(ah[mt][3], al[mt][3], base + (uint32_t)PG * 64u + 32u);
        }
#pragma unroll
        for (int nt = 0; nt < 4; ++nt) {
            int n = warpN * 32 + nt * 8 + g;
            uint32_t nb = bB + (uint32_t)(n * PG + j0) * 8u;
            uint32_t bh0, bl0, bh1, bl1;
            lds64(bh0, bl0, nb);
            lds64(bh1, bl1, nb + 32u);
#pragma unroll
            for (int mt = 0; mt < 2; ++mt) {
                mma16816(acc[mt][nt], ah[mt], bh0, bh1);
                mma16816(acc[mt][nt], ah[mt], bl0, bl1);
                mma16816(acc[mt][nt], al[mt], bh0, bh1);
            }
        }
    }
}

static __device__ __forceinline__ void ldE(const float* __restrict__ E, int m0, int chunk,
                                           float (&e)[16], int tid) {
    int r = tid >> 2, q4 = tid & 3;
    bool ok = (m0 + r) < V_NODES;
    const float4* src = (const float4*)(E + (size_t)(m0 + r) * VD + chunk * 64 + q4 * 16);
#pragma unroll
    for (int q = 0; q < 4; ++q) {
        float4 v = ok ? src[q] : make_float4(0.f, 0.f, 0.f, 0.f);
        e[q * 4 + 0] = v.x; e[q * 4 + 1] = v.y;
        e[q * 4 + 2] = v.z; e[q * 4 + 3] = v.w;
    }
}
static __device__ __forceinline__ void stE(uint32_t aB, const float (&e)[16], int tid) {
    int r = tid >> 2, q4 = tid & 3;
    uint32_t base = aB + (uint32_t)(r * PG1 + q4 * 8) * 8u;
#pragma unroll
    for (int q = 0; q < 8; ++q) {
        uint32_t h, l;
        split2(e[2 * q], e[2 * q + 1], h, l);
        sts64(base + (uint32_t)q * 8u, h, l);
    }
}
static __device__ __forceinline__ void cpB(uint32_t bB, const uint32_t* gsrc,
                                           int tid, int ngran) {
    for (int i = tid; i < ngran; i += NT)
        cpa8(bB + (uint32_t)i * 8u, gsrc + (size_t)i * 2);
}

// phase1: acc += (E tile 128x256) x (W image 256x128), 3xbf16
static __device__ __forceinline__ void phase1(const float* __restrict__ E, int m0,
                                              const uint32_t* __restrict__ bimg,
                                              uint32_t sb, float (&acc)[2][4][4], int tid) {
    int lane = tid & 31, wid = tid >> 5, warpM = wid >> 2, warpN = wid & 3;
    float e[16];
    cpB(sb + OFF_B(0), bimg, tid, CHUNK_B1);
    CP_COMMIT();
    ldE(E, m0, 0, e, tid);
#pragma unroll
    for (int c2 = 0; c2 < 4; ++c2) {
        int b = c2 & 1;
        stE(sb + OFF_A(b), e, tid);
        if (c2 < 3) {
            cpB(sb + OFF_B(b ^ 1), bimg + (size_t)(c2 + 1) * 128 * 70, tid, CHUNK_B1);
            CP_COMMIT();
            CP_WAIT(1);
        } else {
            CP_WAIT(0);
        }
        __syncthreads();
        if (c2 < 3) ldE(E, m0, c2 + 1, e, tid);
        gemm_bufs<PG1, 4>(sb + OFF_A(b), sb + OFF_B(b), acc, lane, warpM, warpN);
        __syncthreads();
    }
}

// -------- trivial kernels --------
__global__ void k_zero(float* __restrict__ out, int n) {
    int i = blockIdx.x * blockDim.x + threadIdx.x;
    if (i < n) out[i] = 0.0f;
}
__global__ void k_offsets(const int* __restrict__ map) {
    int v = blockIdx.x * blockDim.x + threadIdx.x;
    if (v >= V_NODES) return;
    int m = map[v];
    int prev = (v == 0) ? -1 : map[v - 1];
    for (int g = prev + 1; g <= m; ++g) g_start_arr[g] = v;
    if (v == V_NODES - 1)
        for (int g = m + 1; g <= G_NUM; ++g) g_start_arr[g] = V_NODES;
}

__global__ void k_prep(const float* __restrict__ sw1,
                       const float* __restrict__ tw1,
                       const float* __restrict__ tw2) {
    int i = blockIdx.x * blockDim.x + threadIdx.x;
    if (i >= 16384) return;
    {   // W1 images: chunk c, row n, kpair j
        int c = i >> 12, n = (i >> 5) & 127, j = i & 31;
        int k = c * 64 + 2 * j;
        uint32_t h, l;
        int dst = (c * 128 + n) * 70 + 2 * j;
        split2(sw1[(size_t)k * HID + n], sw1[(size_t)(k + 1) * HID + n], h, l);
        g_b1s[dst] = h; g_b1s[dst + 1] = l;
        split2(tw1[(size_t)k * HID + n], tw1[(size_t)(k + 1) * HID + n], h, l);
        g_b1t[dst] = h; g_b1t[dst + 1] = l;
    }
    {   // W2 image: half hf, row n2, kpair j
        int hf = i >> 13, n2 = (i >> 6) & 127, j = i & 63;
        int k = 2 * j, n = hf * 128 + n2;
        uint32_t h, l;
        split2(tw2[(size_t)k * GD + n], tw2[(size_t)(k + 1) * GD + n], h, l);
        int dst = (hf * 128 + n2) * 134 + 2 * j;
        g_b2t[dst] = h; g_b2t[dst + 1] = l;
    }
}

// -------- scoring --------
__global__ void __launch_bounds__(NT) k_scores(const float* __restrict__ E,
                                               const float* __restrict__ W2s) {
    extern __shared__ uint8_t smemraw[];
    uint32_t sb = smem_u32(smemraw);
    __shared__ float sW2[HID * 8];
    __shared__ float sScore[TM * 8];
    int tid = threadIdx.x;
    int m0 = blockIdx.x * TM;
    for (int i = tid; i < HID * 8; i += NT) sW2[i] = W2s[i];
    for (int i = tid; i < TM * 8; i += NT) sScore[i] = 0.f;

    float acc[2][4][4];
#pragma unroll
    for (int a = 0; a < 2; ++a)
#pragma unroll
        for (int b = 0; b < 4; ++b)
#pragma unroll
            for (int q = 0; q < 4; ++q) acc[a][b][q] = 0.f;

    phase1(E, m0, g_b1s, sb, acc, tid);

    // second layer (128 -> 8) from fragments
    int lane = tid & 31, wid = tid >> 5, warpM = wid >> 2, warpN = wid & 3;
    int g = lane >> 2, cc = lane & 3;
    float p[4][8];
#pragma unroll
    for (int r = 0; r < 4; ++r)
#pragma unroll
        for (int h = 0; h < 8; ++h) p[r][h] = 0.f;
#pragma unroll
    for (int mt = 0; mt < 2; ++mt)
#pragma unroll
        for (int nt = 0; nt < 4; ++nt) {
            int c0 = warpN * 32 + nt * 8 + cc * 2;
            float v0 = fmaxf(acc[mt][nt][0], 0.f), v1 = fmaxf(acc[mt][nt][1], 0.f);
            float v2 = fmaxf(acc[mt][nt][2], 0.f), v3 = fmaxf(acc[mt][nt][3], 0.f);
#pragma unroll
            for (int h = 0; h < 8; ++h) {
                p[mt * 2 + 0][h] += v0 * sW2[c0 * 8 + h] + v1 * sW2[c0 * 8 + 8 + h];
                p[mt * 2 + 1][h] += v2 * sW2[c0 * 8 + h] + v3 * sW2[c0 * 8 + 8 + h];
            }
        }
#pragma unroll
    for (int off = 1; off <= 2; off <<= 1)
#pragma unroll
        for (int r = 0; r < 4; ++r)
#pragma unroll
            for (int h = 0; h < 8; ++h)
                p[r][h] += __shfl_xor_sync(0xFFFFFFFFu, p[r][h], off);
    if (cc == 0) {
#pragma unroll
        for (int mt = 0; mt < 2; ++mt)
#pragma unroll
            for (int i2 = 0; i2 < 2; ++i2) {
                int row = warpM * 32 + mt * 16 + i2 * 8 + g;
#pragma unroll
                for (int h = 0; h < 8; ++h)
                    atomicAdd(&sScore[row * 8 + h], p[mt * 2 + i2][h]);
            }
    }
    __syncthreads();
    for (int i = tid; i < TM * 8; i += NT) {
        int v = m0 + (i >> 3);
        if (v < V_NODES) g_scores[(size_t)v * 8 + (i & 7)] = sScore[i];
    }
}

// -------- per-graph softmax stats --------
__global__ void __launch_bounds__(128) k_segstats() {
    int g = blockIdx.x;
    int s = g_start_arr[g], e = g_start_arr[g + 1];
    __shared__ float red[128];
    __shared__ float sm8[8];
    int tid = threadIdx.x, h = tid & 7, k = tid >> 3;

    float mx = -INFINITY;
    for (int v = s + k; v < e; v += 16) mx = fmaxf(mx, g_scores[(size_t)v * 8 + h]);
    red[tid] = mx;
    __syncthreads();
    for (int st = 64; st >= 8; st >>= 1) {
        if (tid < st) red[tid] = fmaxf(red[tid], red[tid + st]);
        __syncthreads();
    }
    if (tid < 8) {
        float m = red[tid];
        if (!isfinite(m)) m = 0.0f;
        sm8[tid] = m;
        g_m[g * 8 + tid] = m;
    }
    __syncthreads();
    float m = sm8[h];
    float sum = 0.f;
    for (int v = s + k; v < e; v += 16) sum += expf(g_scores[(size_t)v * 8 + h] - m);
    red[tid] = sum;
    __syncthreads();
    for (int st = 64; st >= 8; st >>= 1) {
        if (tid < st) red[tid] += red[tid + st];
        __syncthreads();
    }
    if (tid < 8) g_d[g * 8 + tid] = red[tid];
}

// -------- transform + weighting + segment sum --------
__global__ void __launch_bounds__(NT) k_transform(const float* __restrict__ E,
                                                  const int* __restrict__ map,
                                                  float* __restrict__ out) {
    extern __shared__ uint8_t smemraw[];
    uint32_t sb = smem_u32(smemraw);
    float* sR = (float*)smemraw;   // epilogue staging aliases B2h0 region
    __shared__ float swgt[TM * 8];
    __shared__ int smap[TM];
    __shared__ int segStart[TM + 1];
    __shared__ int segGraph[TM];
    __shared__ int nseg;

    int tid = threadIdx.x;
    int m0 = blockIdx.x * TM;

    for (int o = tid; o < TM * 8; o += NT) {
        int row = o >> 3, h = o & 7;
        int v = m0 + row;
        float w = 0.f;
        if (v < V_NODES) {
            int gg = map[v];
            if (h == 0) smap[row] = gg;
            float D = g_d[gg * 8 + h];
            if (D > 0.f)
                w = expf(g_scores[(size_t)v * 8 + h] - g_m[gg * 8 + h]) / D;
        } else if (h == 0) {
            smap[row] = -1;
        }
        swgt[o] = w;
    }
    __syncthreads();
    if (tid == 0) {
        int ns = 0, prev = -2, endr = TM;
        for (int r = 0; r < TM; ++r) {
            int mg = smap[r];
            if (mg < 0) { endr = r; break; }
            if (mg != prev) { segStart[ns] = r; segGraph[ns] = mg; prev = mg; ++ns; }
        }
        segStart[ns] = endr;
        nseg = ns;
    }

    float acc[2][4][4];
#pragma unroll
    for (int a = 0; a < 2; ++a)
#pragma unroll
        for (int b = 0; b < 4; ++b)
#pragma unroll
            for (int q = 0; q < 4; ++q) acc[a][b][q] = 0.f;

    phase1(E, m0, g_b1t, sb, acc, tid);

    int lane = tid & 31, wid = tid >> 5, warpM = wid >> 2, warpN = wid & 3;
    int g = lane >> 2, cc = lane & 3;

    // prefetch B2 halves; write A2 = relu(hidden) hi/lo
    cpB(sb + OFF_B2(0), g_b2t, tid, CHUNK_B2);
    CP_COMMIT();
#pragma unroll
    for (int mt = 0; mt < 2; ++mt)
#pragma unroll
        for (int i2 = 0; i2 < 2; ++i2) {
            int row = warpM * 32 + mt * 16 + i2 * 8 + g;
#pragma unroll
            for (int nt = 0; nt < 4; ++nt) {
                int j = warpN * 16 + nt * 4 + cc;
                float x0 = fmaxf(acc[mt][nt][2 * i2], 0.f);
                float x1 = fmaxf(acc[mt][nt][2 * i2 + 1], 0.f);
                uint32_t h, l;
                split2(x0, x1, h, l);
                sts64(sb + OFF_A2 + (uint32_t)(row * PG2 + j) * 8u, h, l);
            }
        }
    cpB(sb + OFF_B2(1), g_b2t + (size_t)128 * 134, tid, CHUNK_B2);
    CP_COMMIT();
    CP_WAIT(1);
    __syncthreads();

#pragma unroll
    for (int half = 0; half < 2; ++half) {
        if (half == 1) {
            CP_WAIT(0);
            __syncthreads();
        }
#pragma unroll
        for (int a = 0; a < 2; ++a)
#pragma unroll
            for (int b = 0; b < 4; ++b)
#pragma unroll
                for (int q = 0; q < 4; ++q) acc[a][b][q] = 0.f;

        gemm_bufs<PG2, 8>(sb + OFF_A2, sb + OFF_B2(half), acc, lane, warpM, warpN);
        __syncthreads();

        // relu * softmax-weight -> sR
#pragma unroll
        for (int mt = 0; mt < 2; ++mt)
#pragma unroll
            for (int i2 = 0; i2 < 2; ++i2) {
                int row = warpM * 32 + mt * 16 + i2 * 8 + g;
                float w = swgt[row * 8 + half * 4 + warpN];
#pragma unroll
                for (int nt = 0; nt < 4; ++nt) {
                    int col = warpN * 32 + nt * 8 + cc * 2;
                    sR[row * 132 + col]     = fmaxf(acc[mt][nt][2 * i2], 0.f) * w;
                    sR[row * 132 + col + 1] = fmaxf(acc[mt][nt][2 * i2 + 1], 0.f) * w;
                }
            }
        __syncthreads();

        // segment-reduce rows, one atomic per (segment, col)
        {
            int col = tid & 127, slot = tid >> 7;
            for (int sg = slot; sg < nseg; sg += 4) {
                int r0 = segStart[sg], r1 = segStart[sg + 1];
                float s = 0.f;
                for (int r = r0; r < r1; ++r) s += sR[r * 132 + col];
                atomicAdd(&out[(size_t)segGraph[sg] * GD + half * 128 + col], s);
            }
        }
        __syncthreads();
    }
}

// -------- launch --------
extern "C" void kernel_launch(void* const* d_in, const int* in_sizes, int n_in,
                              void* d_out, int out_size) {
    const float* E   = (const float*)d_in[0];
    const int*   map = (const int*)d_in[1];
    int base = (in_sizes[2] == 1) ? 3 : 2;
    const float* sw1 = (const float*)d_in[base + 0];
    const float* sw2 = (const float*)d_in[base + 1];
    const float* tw1 = (const float*)d_in[base + 2];
    const float* tw2 = (const float*)d_in[base + 3];
    float* out = (float*)d_out;

    cudaFuncSetAttribute(k_scores, cudaFuncAttributeMaxDynamicSharedMemorySize,
                         SMEM_SCORES);
    cudaFuncSetAttribute(k_transform, cudaFuncAttributeMaxDynamicSharedMemorySize,
                         SMEM_TRANS);

    int nOut = G_NUM * GD;
    int nTiles = (V_NODES + TM - 1) / TM;

    k_zero<<<(nOut + 255) / 256, 256>>>(out, nOut);
    k_offsets<<<(V_NODES + 255) / 256, 256>>>(map);
    k_prep<<<64, 256>>>(sw1, tw1, tw2);
    k_scores<<<nTiles, NT, SMEM_SCORES>>>(E, sw2);
    k_segstats<<<G_NUM, 128>>>();
    k_transform<<<nTiles, NT, SMEM_TRANS>>>(E, map, out);
}

// round 6
// speedup vs baseline: 1.5369x; 1.0581x over previous
#include <cuda_runtime.h>
#include <cuda_bf16.h>
#include <math.h>
#include <stdint.h>

#define V_NODES 500000
#define VD 256
#define G_NUM 4000
#define H_HEADS 8
#define GD 256
#define HID 128
#define TM 128
#define NT 512

#define PGA  132   // A1 row pitch in 8B granules (128 k-pairs + 4 pad)
#define PGA2 68    // A2 row pitch (64 k-pairs + 4 pad)
#define SMEM_SCORES (128 * PGA * 8)                    // 135168
#define OFF_SR      (128 * PGA * 8)
#define SMEM_TRANS  (135168 + 128 * 132 * 4)           // 202752

// -------- device scratch --------
__device__ float g_scores[(size_t)V_NODES * H_HEADS];
__device__ float g_m[G_NUM * H_HEADS];
__device__ float g_d[G_NUM * H_HEADS];
__device__ int   g_start_arr[G_NUM + 1];
// frag-ordered weight images: entry (ks,n,c) = {bh0, bl0, bh1, bl1}
__device__ uint4 g_b1s[16 * 128 * 4];
__device__ uint4 g_b1t[16 * 128 * 4];
__device__ uint4 g_b2t[2 * 8 * 128 * 4];

// -------- helpers --------
static __device__ __forceinline__ uint32_t smem_u32(const void* p) {
    uint32_t a;
    asm("{ .reg .u64 t; cvta.to.shared.u64 t, %1; cvt.u32.u64 %0, t; }" : "=r"(a) : "l"(p));
    return a;
}
static __device__ __forceinline__ void lds64(uint32_t& a, uint32_t& b, uint32_t addr) {
    asm volatile("ld.shared.v2.b32 {%0,%1}, [%2];" : "=r"(a), "=r"(b) : "r"(addr));
}
static __device__ __forceinline__ void sts64(uint32_t addr, uint32_t a, uint32_t b) {
    asm volatile("st.shared.v2.b32 [%0], {%1,%2};" :: "r"(addr), "r"(a), "r"(b) : "memory");
}
static __device__ __forceinline__ void split2(float x0, float x1, uint32_t& h, uint32_t& l) {
    __nv_bfloat16 h0 = __float2bfloat16(x0), h1 = __float2bfloat16(x1);
    float r0 = x0 - __bfloat162float(h0);
    float r1 = x1 - __bfloat162float(h1);
    __nv_bfloat16 l0 = __float2bfloat16(r0), l1 = __float2bfloat16(r1);
    h = (uint32_t)__bfloat16_as_ushort(h0) | ((uint32_t)__bfloat16_as_ushort(h1) << 16);
    l = (uint32_t)__bfloat16_as_ushort(l0) | ((uint32_t)__bfloat16_as_ushort(l1) << 16);
}
static __device__ __forceinline__ void mma16816(float* d, const uint32_t* a,
                                                uint32_t b0, uint32_t b1) {
    asm volatile("mma.sync.aligned.m16n8k16.row.col.f32.bf16.bf16.f32 "
                 "{%0,%1,%2,%3}, {%4,%5,%6,%7}, {%8,%9}, {%0,%1,%2,%3};"
                 : "+f"(d[0]), "+f"(d[1]), "+f"(d[2]), "+f"(d[3])
                 : "r"(a[0]), "r"(a[1]), "r"(a[2]), "r"(a[3]), "r"(b0), "r"(b1));
}

// GEMM: A from smem (conflict-free, optional swizzle), B direct LDG from frag image.
// Warp computes 32x32. acc[mt][nt][4].
template<int NKS, int PG, int SWZ>
static __device__ __forceinline__ void gemm_direct(uint32_t aB,
                                                   const uint4* __restrict__ bimg,
                                                   float (&acc)[2][4][4],
                                                   int lane, int warpM, int warpN) {
    const int g = lane >> 2, c = lane & 3;
    const uint4* bp = bimg + ((warpN * 32 + g) * 4 + c);
    uint4 bc[4], bn[4];
#pragma unroll
    for (int nt = 0; nt < 4; ++nt) bc[nt] = __ldg(bp + nt * 32);
#pragma unroll
    for (int ks = 0; ks < NKS; ++ks) {
        if (ks + 1 < NKS) {
            const uint4* bq = bp + (ks + 1) * 512;
#pragma unroll
            for (int nt = 0; nt < 4; ++nt) bn[nt] = __ldg(bq + nt * 32);
        }
        int x = SWZ ? (ks >> 2) : 0;
        int j0 = (ks * 8 + c) ^ x;
        uint32_t ah[2][4], al[2][4];
#pragma unroll
        for (int mt = 0; mt < 2; ++mt) {
            int r = warpM * 32 + mt * 16 + g;
            uint32_t base = aB + (uint32_t)(r * PG + j0) * 8u;
            lds64(ah[mt][0], al[mt][0], base);
            lds64(ah[mt][1], al[mt][1], base + (uint32_t)PG * 64u);
            lds64(ah[mt][2], al[mt][2], base + 32u);
            lds64(ah[mt][3], al[mt][3], base + (uint32_t)PG * 64u + 32u);
        }
#pragma unroll
        for (int nt = 0; nt < 4; ++nt)
#pragma unroll
            for (int mt = 0; mt < 2; ++mt) {
                mma16816(acc[mt][nt], ah[mt], bc[nt].x, bc[nt].z);
                mma16816(acc[mt][nt], ah[mt], bc[nt].y, bc[nt].w);
                mma16816(acc[mt][nt], al[mt], bc[nt].x, bc[nt].z);
            }
#pragma unroll
        for (int nt = 0; nt < 4; ++nt) bc[nt] = bn[nt];
    }
}

// stage full 128x256 E tile as interleaved hi/lo pairs, conflict-free XOR layout
static __device__ __forceinline__ void stageE(const float* __restrict__ E, int m0,
                                              uint32_t aB, int tid) {
    int r = tid >> 2, q4 = tid & 3;
    bool ok = (m0 + r) < V_NODES;
    const float4* src = (const float4*)(E + (size_t)(m0 + r) * VD + q4 * 64);
    uint32_t base = aB + (uint32_t)(r * PGA) * 8u;
#pragma unroll
    for (int t = 0; t < 16; ++t) {
        float4 v = ok ? src[t] : make_float4(0.f, 0.f, 0.f, 0.f);
        int j0 = q4 * 32 + 2 * t;
        uint32_t h, l;
        split2(v.x, v.y, h, l);
        sts64(base + (uint32_t)(j0 ^ q4) * 8u, h, l);
        split2(v.z, v.w, h, l);
        sts64(base + (uint32_t)((j0 + 1) ^ q4) * 8u, h, l);
    }
}

// -------- trivial kernels --------
__global__ void k_zero(float* __restrict__ out, int n) {
    int i = blockIdx.x * blockDim.x + threadIdx.x;
    if (i < n) out[i] = 0.0f;
}
__global__ void k_offsets(const int* __restrict__ map) {
    int v = blockIdx.x * blockDim.x + threadIdx.x;
    if (v >= V_NODES) return;
    int m = map[v];
    int prev = (v == 0) ? -1 : map[v - 1];
    for (int g = prev + 1; g <= m; ++g) g_start_arr[g] = v;
    if (v == V_NODES - 1)
        for (int g = m + 1; g <= G_NUM; ++g) g_start_arr[g] = V_NODES;
}

// build frag-ordered hi/lo bf16 weight images
__global__ void k_prep(const float* __restrict__ sw1,
                       const float* __restrict__ tw1,
                       const float* __restrict__ tw2) {
    int i = blockIdx.x * blockDim.x + threadIdx.x;
    if (i >= 8192) return;
    int ks = i >> 9, n = (i >> 2) & 127, c = i & 3;
    int k0 = ks * 16 + 2 * c;
    uint4 e;
    split2(sw1[(size_t)k0 * HID + n], sw1[(size_t)(k0 + 1) * HID + n], e.x, e.y);
    split2(sw1[(size_t)(k0 + 8) * HID + n], sw1[(size_t)(k0 + 9) * HID + n], e.z, e.w);
    g_b1s[i] = e;
    split2(tw1[(size_t)k0 * HID + n], tw1[(size_t)(k0 + 1) * HID + n], e.x, e.y);
    split2(tw1[(size_t)(k0 + 8) * HID + n], tw1[(size_t)(k0 + 9) * HID + n], e.z, e.w);
    g_b1t[i] = e;
    int half = i >> 12, ks2 = (i >> 9) & 7;
    int ng = half * 128 + n, k2 = ks2 * 16 + 2 * c;
    split2(tw2[(size_t)k2 * GD + ng], tw2[(size_t)(k2 + 1) * GD + ng], e.x, e.y);
    split2(tw2[(size_t)(k2 + 8) * GD + ng], tw2[(size_t)(k2 + 9) * GD + ng], e.z, e.w);
    g_b2t[i] = e;
}

// -------- scoring --------
__global__ void __launch_bounds__(NT, 1) k_scores(const float* __restrict__ E,
                                                  const float* __restrict__ W2s) {
    extern __shared__ uint8_t smemraw[];
    uint32_t sb = smem_u32(smemraw);
    __shared__ float sW2[HID * 8];
    __shared__ float sScore[TM * 8];
    int tid = threadIdx.x;
    int m0 = blockIdx.x * TM;
    for (int i = tid; i < HID * 8; i += NT) sW2[i] = W2s[i];
    for (int i = tid; i < TM * 8; i += NT) sScore[i] = 0.f;

    stageE(E, m0, sb, tid);

    float acc[2][4][4];
#pragma unroll
    for (int a = 0; a < 2; ++a)
#pragma unroll
        for (int b = 0; b < 4; ++b)
#pragma unroll
            for (int q = 0; q < 4; ++q) acc[a][b][q] = 0.f;
    __syncthreads();

    int lane = tid & 31, wid = tid >> 5, warpM = wid >> 2, warpN = wid & 3;
    gemm_direct<16, PGA, 1>(sb, g_b1s, acc, lane, warpM, warpN);

    // second layer (128 -> 8) from fragments
    int g = lane >> 2, cc = lane & 3;
    float p[4][8];
#pragma unroll
    for (int r = 0; r < 4; ++r)
#pragma unroll
        for (int h = 0; h < 8; ++h) p[r][h] = 0.f;
#pragma unroll
    for (int mt = 0; mt < 2; ++mt)
#pragma unroll
        for (int nt = 0; nt < 4; ++nt) {
            int c0 = warpN * 32 + nt * 8 + cc * 2;
            float v0 = fmaxf(acc[mt][nt][0], 0.f), v1 = fmaxf(acc[mt][nt][1], 0.f);
            float v2 = fmaxf(acc[mt][nt][2], 0.f), v3 = fmaxf(acc[mt][nt][3], 0.f);
#pragma unroll
            for (int h = 0; h < 8; ++h) {
                p[mt * 2 + 0][h] += v0 * sW2[c0 * 8 + h] + v1 * sW2[c0 * 8 + 8 + h];
                p[mt * 2 + 1][h] += v2 * sW2[c0 * 8 + h] + v3 * sW2[c0 * 8 + 8 + h];
            }
        }
#pragma unroll
    for (int off = 1; off <= 2; off <<= 1)
#pragma unroll
        for (int r = 0; r < 4; ++r)
#pragma unroll
            for (int h = 0; h < 8; ++h)
                p[r][h] += __shfl_xor_sync(0xFFFFFFFFu, p[r][h], off);
    if (cc == 0) {
#pragma unroll
        for (int mt = 0; mt < 2; ++mt)
#pragma unroll
            for (int i2 = 0; i2 < 2; ++i2) {
                int row = warpM * 32 + mt * 16 + i2 * 8 + g;
#pragma unroll
                for (int h = 0; h < 8; ++h)
                    atomicAdd(&sScore[row * 8 + h], p[mt * 2 + i2][h]);
            }
    }
    __syncthreads();
    for (int i = tid; i < TM * 8; i += NT) {
        int v = m0 + (i >> 3);
        if (v < V_NODES) g_scores[(size_t)v * 8 + (i & 7)] = sScore[i];
    }
}

// -------- per-graph softmax stats --------
__global__ void __launch_bounds__(128) k_segstats() {
    int g = blockIdx.x;
    int s = g_start_arr[g], e = g_start_arr[g + 1];
    __shared__ float red[128];
    __shared__ float sm8[8];
    int tid = threadIdx.x, h = tid & 7, k = tid >> 3;

    float mx = -INFINITY;
    for (int v = s + k; v < e; v += 16) mx = fmaxf(mx, g_scores[(size_t)v * 8 + h]);
    red[tid] = mx;
    __syncthreads();
    for (int st = 64; st >= 8; st >>= 1) {
        if (tid < st) red[tid] = fmaxf(red[tid], red[tid + st]);
        __syncthreads();
    }
    if (tid < 8) {
        float m = red[tid];
        if (!isfinite(m)) m = 0.0f;
        sm8[tid] = m;
        g_m[g * 8 + tid] = m;
    }
    __syncthreads();
    float m = sm8[h];
    float sum = 0.f;
    for (int v = s + k; v < e; v += 16) sum += expf(g_scores[(size_t)v * 8 + h] - m);
    red[tid] = sum;
    __syncthreads();
    for (int st = 64; st >= 8; st >>= 1) {
        if (tid < st) red[tid] += red[tid + st];
        __syncthreads();
    }
    if (tid < 8) g_d[g * 8 + tid] = red[tid];
}

// -------- transform + weighting + segment sum --------
__global__ void __launch_bounds__(NT, 1) k_transform(const float* __restrict__ E,
                                                     const int* __restrict__ map,
                                                     float* __restrict__ out) {
    extern __shared__ uint8_t smemraw[];
    uint32_t sb = smem_u32(smemraw);
    float* sR = (float*)(smemraw + OFF_SR);
    __shared__ float swgt[TM * 8];
    __shared__ int smap[TM];
    __shared__ int segStart[TM + 1];
    __shared__ int segGraph[TM];
    __shared__ int nseg;

    int tid = threadIdx.x;
    int m0 = blockIdx.x * TM;

    for (int o = tid; o < TM * 8; o += NT) {
        int row = o >> 3, h = o & 7;
        int v = m0 + row;
        float w = 0.f;
        if (v < V_NODES) {
            int gg = map[v];
            if (h == 0) smap[row] = gg;
            float D = g_d[gg * 8 + h];
            if (D > 0.f)
                w = expf(g_scores[(size_t)v * 8 + h] - g_m[gg * 8 + h]) / D;
        } else if (h == 0) {
            smap[row] = -1;
        }
        swgt[o] = w;
    }
    __syncthreads();
    if (tid == 0) {
        int ns = 0, prev = -2, endr = TM;
        for (int r = 0; r < TM; ++r) {
            int mg = smap[r];
            if (mg < 0) { endr = r; break; }
            if (mg != prev) { segStart[ns] = r; segGraph[ns] = mg; prev = mg; ++ns; }
        }
        segStart[ns] = endr;
        nseg = ns;
    }

    stageE(E, m0, sb, tid);

    float acc[2][4][4];
#pragma unroll
    for (int a = 0; a < 2; ++a)
#pragma unroll
        for (int b = 0; b < 4; ++b)
#pragma unroll
            for (int q = 0; q < 4; ++q) acc[a][b][q] = 0.f;
    __syncthreads();

    int lane = tid & 31, wid = tid >> 5, warpM = wid >> 2, warpN = wid & 3;
    int g = lane >> 2, cc = lane & 3;

    gemm_direct<16, PGA, 1>(sb, g_b1t, acc, lane, warpM, warpN);
    __syncthreads();   // A1 dead; safe to overwrite with A2

    // A2 = relu(hidden) hi/lo, natural conflict-free layout (pitch PGA2)
#pragma unroll
    for (int mt = 0; mt < 2; ++mt)
#pragma unroll
        for (int i2 = 0; i2 < 2; ++i2) {
            int row = warpM * 32 + mt * 16 + i2 * 8 + g;
#pragma unroll
            for (int nt = 0; nt < 4; ++nt) {
                int g2 = warpN * 16 + nt * 4 + cc;
                float x0 = fmaxf(acc[mt][nt][2 * i2], 0.f);
                float x1 = fmaxf(acc[mt][nt][2 * i2 + 1], 0.f);
                uint32_t h, l;
                split2(x0, x1, h, l);
                sts64(sb + (uint32_t)(row * PGA2 + g2) * 8u, h, l);
            }
        }
    __syncthreads();

#pragma unroll
    for (int half = 0; half < 2; ++half) {
#pragma unroll
        for (int a = 0; a < 2; ++a)
#pragma unroll
            for (int b = 0; b < 4; ++b)
#pragma unroll
                for (int q = 0; q < 4; ++q) acc[a][b][q] = 0.f;

        gemm_direct<8, PGA2, 0>(sb, g_b2t + half * 4096, acc, lane, warpM, warpN);

        // relu * softmax-weight -> sR
#pragma unroll
        for (int mt = 0; mt < 2; ++mt)
#pragma unroll
            for (int i2 = 0; i2 < 2; ++i2) {
                int row = warpM * 32 + mt * 16 + i2 * 8 + g;
                float w = swgt[row * 8 + half * 4 + warpN];
#pragma unroll
                for (int nt = 0; nt < 4; ++nt) {
                    int col = warpN * 32 + nt * 8 + cc * 2;
                    sR[row * 132 + col]     = fmaxf(acc[mt][nt][2 * i2], 0.f) * w;
                    sR[row * 132 + col + 1] = fmaxf(acc[mt][nt][2 * i2 + 1], 0.f) * w;
                }
            }
        __syncthreads();

        // segment-reduce rows, one atomic per (segment, col)
        {
            int col = tid & 127, slot = tid >> 7;
            for (int sg = slot; sg < nseg; sg += 4) {
                int r0 = segStart[sg], r1 = segStart[sg + 1];
                float s = 0.f;
                for (int r = r0; r < r1; ++r) s += sR[r * 132 + col];
                atomicAdd(&out[(size_t)segGraph[sg] * GD + half * 128 + col], s);
            }
        }
        __syncthreads();
    }
}

// -------- launch --------
extern "C" void kernel_launch(void* const* d_in, const int* in_sizes, int n_in,
                              void* d_out, int out_size) {
    const float* E   = (const float*)d_in[0];
    const int*   map = (const int*)d_in[1];
    int base = (in_sizes[2] == 1) ? 3 : 2;
    const float* sw1 = (const float*)d_in[base + 0];
    const float* sw2 = (const float*)d_in[base + 1];
    const float* tw1 = (const float*)d_in[base + 2];
    const float* tw2 = (const float*)d_in[base + 3];
    float* out = (float*)d_out;

    cudaFuncSetAttribute(k_scores, cudaFuncAttributeMaxDynamicSharedMemorySize,
                         SMEM_SCORES);
    cudaFuncSetAttribute(k_transform, cudaFuncAttributeMaxDynamicSharedMemorySize,
                         SMEM_TRANS);

    int nOut = G_NUM * GD;
    int nTiles = (V_NODES + TM - 1) / TM;

    k_zero<<<(nOut + 255) / 256, 256>>>(out, nOut);
    k_offsets<<<(V_NODES + 255) / 256, 256>>>(map);
    k_prep<<<32, 256>>>(sw1, tw1, tw2);
    k_scores<<<nTiles, NT, SMEM_SCORES>>>(E, sw2);
    k_segstats<<<G_NUM, 128>>>();
    k_transform<<<nTiles, NT, SMEM_TRANS>>>(E, map, out);
}

// round 7
// speedup vs baseline: 1.7666x; 1.1495x over previous
#include <cuda_runtime.h>
#include <cuda_bf16.h>
#include <math.h>
#include <stdint.h>

#define V_NODES 500000
#define VD 256
#define G_NUM 4000
#define H_HEADS 8
#define GD 256
#define HID 128
#define TM 128
#define NT 512

#define PGA  132   // A1 row pitch in 8B granules (128 k-pairs + 4 pad)
#define PGA2 68    // A2 row pitch (64 k-pairs + 4 pad)
#define SMEM_MAIN   (128 * PGA * 8)                    // 135168
#define OFF_SR2     (128 * PGA2 * 8)                   // 69632
#define SMEM_TRANS2 (OFF_SR2 + 128 * 132 * 4)          // 137216

// -------- device scratch --------
__device__ float g_scores[(size_t)V_NODES * H_HEADS];
__device__ float g_m[G_NUM * H_HEADS];
__device__ float g_d[G_NUM * H_HEADS];
__device__ int   g_start_arr[G_NUM + 1];
// hidden_t = relu(E @ W1t) as hi/lo bf16 pairs, phase2-A fragment layout
__device__ uint2 g_hidden[(size_t)V_NODES * 64];
// frag-ordered weight images: entry (ks,n,c) = {bh0, bl0, bh1, bl1}
__device__ uint4 g_b1s[16 * 128 * 4];
__device__ uint4 g_b1t[16 * 128 * 4];
__device__ uint4 g_b2t[2 * 8 * 128 * 4];

// -------- helpers --------
static __device__ __forceinline__ uint32_t smem_u32(const void* p) {
    uint32_t a;
    asm("{ .reg .u64 t; cvta.to.shared.u64 t, %1; cvt.u32.u64 %0, t; }" : "=r"(a) : "l"(p));
    return a;
}
static __device__ __forceinline__ void lds64(uint32_t& a, uint32_t& b, uint32_t addr) {
    asm volatile("ld.shared.v2.b32 {%0,%1}, [%2];" : "=r"(a), "=r"(b) : "r"(addr));
}
static __device__ __forceinline__ void sts64(uint32_t addr, uint32_t a, uint32_t b) {
    asm volatile("st.shared.v2.b32 [%0], {%1,%2};" :: "r"(addr), "r"(a), "r"(b) : "memory");
}
static __device__ __forceinline__ void cpa16(uint32_t s, const void* g) {
    asm volatile("{ .reg .u64 gp; cvta.to.global.u64 gp, %1; "
                 "cp.async.cg.shared.global [%0], [gp], 16; }"
                 :: "r"(s), "l"(g) : "memory");
}
#define CP_COMMIT() asm volatile("cp.async.commit_group;" ::: "memory")
#define CP_WAIT0()  asm volatile("cp.async.wait_group 0;" ::: "memory")

static __device__ __forceinline__ void split2(float x0, float x1, uint32_t& h, uint32_t& l) {
    __nv_bfloat16 h0 = __float2bfloat16(x0), h1 = __float2bfloat16(x1);
    float r0 = x0 - __bfloat162float(h0);
    float r1 = x1 - __bfloat162float(h1);
    __nv_bfloat16 l0 = __float2bfloat16(r0), l1 = __float2bfloat16(r1);
    h = (uint32_t)__bfloat16_as_ushort(h0) | ((uint32_t)__bfloat16_as_ushort(h1) << 16);
    l = (uint32_t)__bfloat16_as_ushort(l0) | ((uint32_t)__bfloat16_as_ushort(l1) << 16);
}
static __device__ __forceinline__ void mma16816(float* d, const uint32_t* a,
                                                uint32_t b0, uint32_t b1) {
    asm volatile("mma.sync.aligned.m16n8k16.row.col.f32.bf16.bf16.f32 "
                 "{%0,%1,%2,%3}, {%4,%5,%6,%7}, {%8,%9}, {%0,%1,%2,%3};"
                 : "+f"(d[0]), "+f"(d[1]), "+f"(d[2]), "+f"(d[3])
                 : "r"(a[0]), "r"(a[1]), "r"(a[2]), "r"(a[3]), "r"(b0), "r"(b1));
}

// GEMM: A from smem (conflict-free, optional per-4ks XOR swizzle), B direct LDG
// from frag image. Warp computes 32x32. acc[mt][nt][4].
// Addresses: 1 A-row base reg, literal offsets inside unrolled blocks.
template<int NKS, int PG, int SWZ>
static __device__ __forceinline__ void gemm_direct(uint32_t aB,
                                                   const uint4* __restrict__ bimg,
                                                   float (&acc)[2][4][4],
                                                   int lane, int warpM, int warpN) {
    const int g = lane >> 2, c = lane & 3;
    const uint4* bp = bimg + ((warpN * 32 + g) * 4 + c);
    const uint32_t aRow = aB + (uint32_t)((warpM * 32 + g) * PG) * 8u;
    uint4 bc[4], bn[4];
#pragma unroll
    for (int nt = 0; nt < 4; ++nt) bc[nt] = __ldg(bp + nt * 32);
#pragma unroll
    for (int x = 0; x < NKS / 4; ++x) {
        const uint32_t b0 = aRow + (uint32_t)((x * 32 + c) ^ (SWZ ? x : 0)) * 8u;
#pragma unroll
        for (int i = 0; i < 4; ++i) {
            const int ks = x * 4 + i;
            if (ks + 1 < NKS) {
#pragma unroll
                for (int nt = 0; nt < 4; ++nt)
                    bn[nt] = __ldg(bp + (ks + 1) * 512 + nt * 32);
            }
            uint32_t ah[2][4], al[2][4];
#pragma unroll
            for (int mt = 0; mt < 2; ++mt) {
                uint32_t base = b0 + (uint32_t)(mt * PG * 128 + i * 64);
                lds64(ah[mt][0], al[mt][0], base);
                lds64(ah[mt][1], al[mt][1], base + (uint32_t)PG * 64u);
                lds64(ah[mt][2], al[mt][2], base + 32u);
                lds64(ah[mt][3], al[mt][3], base + (uint32_t)PG * 64u + 32u);
            }
#pragma unroll
            for (int nt = 0; nt < 4; ++nt)
#pragma unroll
                for (int mt = 0; mt < 2; ++mt) {
                    mma16816(acc[mt][nt], ah[mt], bc[nt].x, bc[nt].z);
                    mma16816(acc[mt][nt], ah[mt], bc[nt].y, bc[nt].w);
                    mma16816(acc[mt][nt], al[mt], bc[nt].x, bc[nt].z);
                }
#pragma unroll
            for (int nt = 0; nt < 4; ++nt) bc[nt] = bn[nt];
        }
    }
}

// stage full 128x256 E tile as interleaved hi/lo pairs, conflict-free XOR layout
static __device__ __forceinline__ void stageE(const float* __restrict__ E, int m0,
                                              uint32_t aB, int tid) {
    int r = tid >> 2, q4 = tid & 3;
    bool ok = (m0 + r) < V_NODES;
    const float4* src = (const float4*)(E + (size_t)(m0 + r) * VD + q4 * 64);
    uint32_t base = aB + (uint32_t)(r * PGA) * 8u;
#pragma unroll
    for (int t = 0; t < 16; ++t) {
        float4 v = ok ? src[t] : make_float4(0.f, 0.f, 0.f, 0.f);
        int j0 = q4 * 32 + 2 * t;
        uint32_t h, l;
        split2(v.x, v.y, h, l);
        sts64(base + (uint32_t)(j0 ^ q4) * 8u, h, l);
        split2(v.z, v.w, h, l);
        sts64(base + (uint32_t)((j0 + 1) ^ q4) * 8u, h, l);
    }
}

// -------- trivial kernels --------
__global__ void k_zero(float* __restrict__ out, int n) {
    int i = blockIdx.x * blockDim.x + threadIdx.x;
    if (i < n) out[i] = 0.0f;
}
__global__ void k_offsets(const int* __restrict__ map) {
    int v = blockIdx.x * blockDim.x + threadIdx.x;
    if (v >= V_NODES) return;
    int m = map[v];
    int prev = (v == 0) ? -1 : map[v - 1];
    for (int g = prev + 1; g <= m; ++g) g_start_arr[g] = v;
    if (v == V_NODES - 1)
        for (int g = m + 1; g <= G_NUM; ++g) g_start_arr[g] = V_NODES;
}

// build frag-ordered hi/lo bf16 weight images
__global__ void k_prep(const float* __restrict__ sw1,
                       const float* __restrict__ tw1,
                       const float* __restrict__ tw2) {
    int i = blockIdx.x * blockDim.x + threadIdx.x;
    if (i >= 8192) return;
    int ks = i >> 9, n = (i >> 2) & 127, c = i & 3;
    int k0 = ks * 16 + 2 * c;
    uint4 e;
    split2(sw1[(size_t)k0 * HID + n], sw1[(size_t)(k0 + 1) * HID + n], e.x, e.y);
    split2(sw1[(size_t)(k0 + 8) * HID + n], sw1[(size_t)(k0 + 9) * HID + n], e.z, e.w);
    g_b1s[i] = e;
    split2(tw1[(size_t)k0 * HID + n], tw1[(size_t)(k0 + 1) * HID + n], e.x, e.y);
    split2(tw1[(size_t)(k0 + 8) * HID + n], tw1[(size_t)(k0 + 9) * HID + n], e.z, e.w);
    g_b1t[i] = e;
    int half = i >> 12, ks2 = (i >> 9) & 7;
    int ng = half * 128 + n, k2 = ks2 * 16 + 2 * c;
    split2(tw2[(size_t)k2 * GD + ng], tw2[(size_t)(k2 + 1) * GD + ng], e.x, e.y);
    split2(tw2[(size_t)(k2 + 8) * GD + ng], tw2[(size_t)(k2 + 9) * GD + ng], e.z, e.w);
    g_b2t[i] = e;
}

// -------- fused: scores + hidden_t --------
__global__ void __launch_bounds__(NT, 1) k_main(const float* __restrict__ E,
                                                const float* __restrict__ W2s) {
    extern __shared__ uint8_t smemraw[];
    uint32_t sb = smem_u32(smemraw);
    __shared__ float sW2[HID * 8];
    __shared__ float sScore[TM * 8];
    int tid = threadIdx.x;
    int m0 = blockIdx.x * TM;
    for (int i = tid; i < HID * 8; i += NT) sW2[i] = W2s[i];
    for (int i = tid; i < TM * 8; i += NT) sScore[i] = 0.f;

    stageE(E, m0, sb, tid);

    int lane = tid & 31, wid = tid >> 5, warpM = wid >> 2, warpN = wid & 3;
    int g = lane >> 2, cc = lane & 3;

    float acc[2][4][4];
#pragma unroll
    for (int a = 0; a < 2; ++a)
#pragma unroll
        for (int b = 0; b < 4; ++b)
#pragma unroll
            for (int q = 0; q < 4; ++q) acc[a][b][q] = 0.f;
    __syncthreads();

    // ---- GEMM 1: hidden_t = relu(E @ W1t) -> g_hidden (phase2 frag layout) ----
    gemm_direct<16, PGA, 1>(sb, g_b1t, acc, lane, warpM, warpN);
#pragma unroll
    for (int mt = 0; mt < 2; ++mt)
#pragma unroll
        for (int i2 = 0; i2 < 2; ++i2) {
            int v = m0 + warpM * 32 + mt * 16 + i2 * 8 + g;
            if (v < V_NODES) {
#pragma unroll
                for (int nt = 0; nt < 4; ++nt) {
                    int g2 = warpN * 16 + nt * 4 + cc;
                    float x0 = fmaxf(acc[mt][nt][2 * i2], 0.f);
                    float x1 = fmaxf(acc[mt][nt][2 * i2 + 1], 0.f);
                    uint2 hl;
                    split2(x0, x1, hl.x, hl.y);
                    g_hidden[(size_t)v * 64 + g2] = hl;
                }
            }
        }

    // ---- GEMM 2: scores = relu(E @ W1s) @ W2s ----
#pragma unroll
    for (int a = 0; a < 2; ++a)
#pragma unroll
        for (int b = 0; b < 4; ++b)
#pragma unroll
            for (int q = 0; q < 4; ++q) acc[a][b][q] = 0.f;
    gemm_direct<16, PGA, 1>(sb, g_b1s, acc, lane, warpM, warpN);

    float p[4][8];
#pragma unroll
    for (int r = 0; r < 4; ++r)
#pragma unroll
        for (int h = 0; h < 8; ++h) p[r][h] = 0.f;
#pragma unroll
    for (int mt = 0; mt < 2; ++mt)
#pragma unroll
        for (int nt = 0; nt < 4; ++nt) {
            int c0 = warpN * 32 + nt * 8 + cc * 2;
            float v0 = fmaxf(acc[mt][nt][0], 0.f), v1 = fmaxf(acc[mt][nt][1], 0.f);
            float v2 = fmaxf(acc[mt][nt][2], 0.f), v3 = fmaxf(acc[mt][nt][3], 0.f);
#pragma unroll
            for (int h = 0; h < 8; ++h) {
                p[mt * 2 + 0][h] += v0 * sW2[c0 * 8 + h] + v1 * sW2[c0 * 8 + 8 + h];
                p[mt * 2 + 1][h] += v2 * sW2[c0 * 8 + h] + v3 * sW2[c0 * 8 + 8 + h];
            }
        }
#pragma unroll
    for (int off = 1; off <= 2; off <<= 1)
#pragma unroll
        for (int r = 0; r < 4; ++r)
#pragma unroll
            for (int h = 0; h < 8; ++h)
                p[r][h] += __shfl_xor_sync(0xFFFFFFFFu, p[r][h], off);
    if (cc == 0) {
#pragma unroll
        for (int mt = 0; mt < 2; ++mt)
#pragma unroll
            for (int i2 = 0; i2 < 2; ++i2) {
                int row = warpM * 32 + mt * 16 + i2 * 8 + g;
#pragma unroll
                for (int h = 0; h < 8; ++h)
                    atomicAdd(&sScore[row * 8 + h], p[mt * 2 + i2][h]);
            }
    }
    __syncthreads();
    for (int i = tid; i < TM * 8; i += NT) {
        int v = m0 + (i >> 3);
        if (v < V_NODES) g_scores[(size_t)v * 8 + (i & 7)] = sScore[i];
    }
}

// -------- per-graph softmax stats --------
__global__ void __launch_bounds__(128) k_segstats() {
    int g = blockIdx.x;
    int s = g_start_arr[g], e = g_start_arr[g + 1];
    __shared__ float red[128];
    __shared__ float sm8[8];
    int tid = threadIdx.x, h = tid & 7, k = tid >> 3;

    float mx = -INFINITY;
    for (int v = s + k; v < e; v += 16) mx = fmaxf(mx, g_scores[(size_t)v * 8 + h]);
    red[tid] = mx;
    __syncthreads();
    for (int st = 64; st >= 8; st >>= 1) {
        if (tid < st) red[tid] = fmaxf(red[tid], red[tid + st]);
        __syncthreads();
    }
    if (tid < 8) {
        float m = red[tid];
        if (!isfinite(m)) m = 0.0f;
        sm8[tid] = m;
        g_m[g * 8 + tid] = m;
    }
    __syncthreads();
    float m = sm8[h];
    float sum = 0.f;
    for (int v = s + k; v < e; v += 16) sum += expf(g_scores[(size_t)v * 8 + h] - m);
    red[tid] = sum;
    __syncthreads();
    for (int st = 64; st >= 8; st >>= 1) {
        if (tid < st) red[tid] += red[tid + st];
        __syncthreads();
    }
    if (tid < 8) g_d[g * 8 + tid] = red[tid];
}

// -------- phase2: out += segsum( softmax_w * relu(hidden @ W2t) ) --------
__global__ void __launch_bounds__(NT, 1) k_transform2(const int* __restrict__ map,
                                                      float* __restrict__ out) {
    extern __shared__ uint8_t smemraw[];
    uint32_t sb = smem_u32(smemraw);
    float* sR = (float*)(smemraw + OFF_SR2);
    __shared__ float swgt[TM * 8];
    __shared__ int smap[TM];
    __shared__ int segStart[TM + 1];
    __shared__ int segGraph[TM];
    __shared__ int nseg;

    int tid = threadIdx.x;
    int m0 = blockIdx.x * TM;

    // async-load hidden tile into A2 (pitch PGA2, natural layout)
    for (int i = tid; i < 4096; i += NT) {
        int row = i >> 5, ch = i & 31;
        int v = m0 + row;
        if (v > V_NODES - 1) v = V_NODES - 1;   // clamp; rows past end never read
        cpa16(sb + (uint32_t)(row * PGA2 + ch * 2) * 8u,
              &g_hidden[(size_t)v * 64 + ch * 2]);
    }
    CP_COMMIT();

    for (int o = tid; o < TM * 8; o += NT) {
        int row = o >> 3, h = o & 7;
        int v = m0 + row;
        float w = 0.f;
        if (v < V_NODES) {
            int gg = map[v];
            if (h == 0) smap[row] = gg;
            float D = g_d[gg * 8 + h];
            if (D > 0.f)
                w = expf(g_scores[(size_t)v * 8 + h] - g_m[gg * 8 + h]) / D;
        } else if (h == 0) {
            smap[row] = -1;
        }
        swgt[o] = w;
    }
    __syncthreads();
    if (tid == 0) {
        int ns = 0, prev = -2, endr = TM;
        for (int r = 0; r < TM; ++r) {
            int mg = smap[r];
            if (mg < 0) { endr = r; break; }
            if (mg != prev) { segStart[ns] = r; segGraph[ns] = mg; prev = mg; ++ns; }
        }
        segStart[ns] = endr;
        nseg = ns;
    }
    CP_WAIT0();
    __syncthreads();

    int lane = tid & 31, wid = tid >> 5, warpM = wid >> 2, warpN = wid & 3;
    int g = lane >> 2, cc = lane & 3;

    float acc[2][4][4];
#pragma unroll
    for (int half = 0; half < 2; ++half) {
#pragma unroll
        for (int a = 0; a < 2; ++a)
#pragma unroll
            for (int b = 0; b < 4; ++b)
#pragma unroll
                for (int q = 0; q < 4; ++q) acc[a][b][q] = 0.f;

        gemm_direct<8, PGA2, 0>(sb, g_b2t + half * 4096, acc, lane, warpM, warpN);

        // relu * softmax-weight -> sR
#pragma unroll
        for (int mt = 0; mt < 2; ++mt)
#pragma unroll
            for (int i2 = 0; i2 < 2; ++i2) {
                int row = warpM * 32 + mt * 16 + i2 * 8 + g;
                float w = swgt[row * 8 + half * 4 + warpN];
#pragma unroll
                for (int nt = 0; nt < 4; ++nt) {
                    int col = warpN * 32 + nt * 8 + cc * 2;
                    sR[row * 132 + col]     = fmaxf(acc[mt][nt][2 * i2], 0.f) * w;
                    sR[row * 132 + col + 1] = fmaxf(acc[mt][nt][2 * i2 + 1], 0.f) * w;
                }
            }
        __syncthreads();

        // segment-reduce rows, one atomic per (segment, col)
        {
            int col = tid & 127, slot = tid >> 7;
            for (int sg = slot; sg < nseg; sg += 4) {
                int r0 = segStart[sg], r1 = segStart[sg + 1];
                float s = 0.f;
                for (int r = r0; r < r1; ++r) s += sR[r * 132 + col];
                atomicAdd(&out[(size_t)segGraph[sg] * GD + half * 128 + col], s);
            }
        }
        __syncthreads();
    }
}

// -------- launch --------
extern "C" void kernel_launch(void* const* d_in, const int* in_sizes, int n_in,
                              void* d_out, int out_size) {
    const float* E   = (const float*)d_in[0];
    const int*   map = (const int*)d_in[1];
    int base = (in_sizes[2] == 1) ? 3 : 2;
    const float* sw1 = (const float*)d_in[base + 0];
    const float* sw2 = (const float*)d_in[base + 1];
    const float* tw1 = (const float*)d_in[base + 2];
    const float* tw2 = (const float*)d_in[base + 3];
    float* out = (float*)d_out;

    cudaFuncSetAttribute(k_main, cudaFuncAttributeMaxDynamicSharedMemorySize,
                         SMEM_MAIN);
    cudaFuncSetAttribute(k_transform2, cudaFuncAttributeMaxDynamicSharedMemorySize,
                         SMEM_TRANS2);

    int nOut = G_NUM * GD;
    int nTiles = (V_NODES + TM - 1) / TM;

    k_zero<<<(nOut + 255) / 256, 256>>>(out, nOut);
    k_offsets<<<(V_NODES + 255) / 256, 256>>>(map);
    k_prep<<<32, 256>>>(sw1, tw1, tw2);
    k_main<<<nTiles, NT, SMEM_MAIN>>>(E, sw2);
    k_segstats<<<G_NUM, 128>>>();
    k_transform2<<<nTiles, NT, SMEM_TRANS2>>>(map, out);
}

// round 8
// speedup vs baseline: 1.7739x; 1.0042x over previous
#include <cuda_runtime.h>
#include <cuda_bf16.h>
#include <math.h>
#include <stdint.h>

#define V_NODES 500000
#define VD 256
#define G_NUM 4000
#define H_HEADS 8
#define GD 256
#define HID 128
#define TM 128
#define NT 512

#define PGA  132   // A1 row pitch in 8B granules (128 k-pairs + 4 pad)
#define PGA2 68    // A2 row pitch (64 k-pairs + 4 pad)
#define SMEM_MAIN   (128 * PGA * 8)                    // 135168
#define OFF_SR2     (128 * PGA2 * 8)                   // 69632
#define SMEM_TRANS2 (OFF_SR2 + 128 * 132 * 4)          // 137216

// -------- device scratch --------
__device__ float g_scores[(size_t)V_NODES * H_HEADS];
__device__ float g_m[G_NUM * H_HEADS];
__device__ float g_d[G_NUM * H_HEADS];
__device__ int   g_start_arr[G_NUM + 1];
// hidden_t = relu(E @ W1t) as hi/lo bf16 pairs, phase2-A fragment layout
__device__ uint2 g_hidden[(size_t)V_NODES * 64];
// frag-ordered weight images: entry (ks,n,c) = {bh0, bl0, bh1, bl1}
__device__ uint4 g_b1s[16 * 128 * 4];
__device__ uint4 g_b1t[16 * 128 * 4];
__device__ uint4 g_b2t[2 * 8 * 128 * 4];

// -------- helpers --------
static __device__ __forceinline__ uint32_t smem_u32(const void* p) {
    uint32_t a;
    asm("{ .reg .u64 t; cvta.to.shared.u64 t, %1; cvt.u32.u64 %0, t; }" : "=r"(a) : "l"(p));
    return a;
}
static __device__ __forceinline__ void lds64(uint32_t& a, uint32_t& b, uint32_t addr) {
    asm volatile("ld.shared.v2.b32 {%0,%1}, [%2];" : "=r"(a), "=r"(b) : "r"(addr));
}
static __device__ __forceinline__ void sts64(uint32_t addr, uint32_t a, uint32_t b) {
    asm volatile("st.shared.v2.b32 [%0], {%1,%2};" :: "r"(addr), "r"(a), "r"(b) : "memory");
}
static __device__ __forceinline__ void cpa16(uint32_t s, const void* g) {
    asm volatile("{ .reg .u64 gp; cvta.to.global.u64 gp, %1; "
                 "cp.async.cg.shared.global [%0], [gp], 16; }"
                 :: "r"(s), "l"(g) : "memory");
}
#define CP_COMMIT() asm volatile("cp.async.commit_group;" ::: "memory")
#define CP_WAIT0()  asm volatile("cp.async.wait_group 0;" ::: "memory")

static __device__ __forceinline__ void split2(float x0, float x1, uint32_t& h, uint32_t& l) {
    __nv_bfloat16 h0 = __float2bfloat16(x0), h1 = __float2bfloat16(x1);
    float r0 = x0 - __bfloat162float(h0);
    float r1 = x1 - __bfloat162float(h1);
    __nv_bfloat16 l0 = __float2bfloat16(r0), l1 = __float2bfloat16(r1);
    h = (uint32_t)__bfloat16_as_ushort(h0) | ((uint32_t)__bfloat16_as_ushort(h1) << 16);
    l = (uint32_t)__bfloat16_as_ushort(l0) | ((uint32_t)__bfloat16_as_ushort(l1) << 16);
}
static __device__ __forceinline__ void mma16816(float* d, const uint32_t* a,
                                                uint32_t b0, uint32_t b1) {
    asm volatile("mma.sync.aligned.m16n8k16.row.col.f32.bf16.bf16.f32 "
                 "{%0,%1,%2,%3}, {%4,%5,%6,%7}, {%8,%9}, {%0,%1,%2,%3};"
                 : "+f"(d[0]), "+f"(d[1]), "+f"(d[2]), "+f"(d[3])
                 : "r"(a[0]), "r"(a[1]), "r"(a[2]), "r"(a[3]), "r"(b0), "r"(b1));
}

// GEMM: A from smem (conflict-free, optional per-4ks XOR swizzle), B direct LDG
// from frag image. Warp computes 32x32. acc[mt][nt][4].
// MMAs issued product-major (8 independent tiles between dependent writes);
// A fragments software-pipelined one ks ahead.
template<int NKS, int PG, int SWZ>
static __device__ __forceinline__ void gemm_direct(uint32_t aB,
                                                   const uint4* __restrict__ bimg,
                                                   float (&acc)[2][4][4],
                                                   int lane, int warpM, int warpN) {
    const int g = lane >> 2, c = lane & 3;
    const uint4* bp = bimg + ((warpN * 32 + g) * 4 + c);
    const uint32_t aRow = aB + (uint32_t)((warpM * 32 + g) * PG) * 8u;
    uint4 bc[4], bn[4];
    uint32_t ah[2][2][4], al[2][2][4];   // [buf][mt][frag]

#define LOAD_A(buf, ksv) do { \
    const int x_ = SWZ ? ((ksv) >> 2) : 0; \
    const uint32_t j_ = (uint32_t)((((ksv) * 8) + c) ^ x_) * 8u; \
    _Pragma("unroll") \
    for (int mt = 0; mt < 2; ++mt) { \
        uint32_t base = aRow + j_ + (uint32_t)(mt * PG * 128); \
        lds64(ah[buf][mt][0], al[buf][mt][0], base); \
        lds64(ah[buf][mt][1], al[buf][mt][1], base + (uint32_t)PG * 64u); \
        lds64(ah[buf][mt][2], al[buf][mt][2], base + 32u); \
        lds64(ah[buf][mt][3], al[buf][mt][3], base + (uint32_t)PG * 64u + 32u); \
    } } while (0)

#pragma unroll
    for (int nt = 0; nt < 4; ++nt) bc[nt] = __ldg(bp + nt * 32);
    LOAD_A(0, 0);
#pragma unroll
    for (int ks = 0; ks < NKS; ++ks) {
        const int cur = ks & 1, nxt = cur ^ 1;
        if (ks + 1 < NKS) {
#pragma unroll
            for (int nt = 0; nt < 4; ++nt)
                bn[nt] = __ldg(bp + (ks + 1) * 512 + nt * 32);
            LOAD_A(nxt, ks + 1);
        }
        // product 0: ah x bh
#pragma unroll
        for (int nt = 0; nt < 4; ++nt)
#pragma unroll
            for (int mt = 0; mt < 2; ++mt)
                mma16816(acc[mt][nt], ah[cur][mt], bc[nt].x, bc[nt].z);
        // product 1: ah x bl
#pragma unroll
        for (int nt = 0; nt < 4; ++nt)
#pragma unroll
            for (int mt = 0; mt < 2; ++mt)
                mma16816(acc[mt][nt], ah[cur][mt], bc[nt].y, bc[nt].w);
        // product 2: al x bh
#pragma unroll
        for (int nt = 0; nt < 4; ++nt)
#pragma unroll
            for (int mt = 0; mt < 2; ++mt)
                mma16816(acc[mt][nt], al[cur][mt], bc[nt].x, bc[nt].z);
#pragma unroll
        for (int nt = 0; nt < 4; ++nt) bc[nt] = bn[nt];
    }
#undef LOAD_A
}

// stage full 128x256 E tile as interleaved hi/lo pairs, conflict-free XOR layout
static __device__ __forceinline__ void stageE(const float* __restrict__ E, int m0,
                                              uint32_t aB, int tid) {
    int r = tid >> 2, q4 = tid & 3;
    bool ok = (m0 + r) < V_NODES;
    const float4* src = (const float4*)(E + (size_t)(m0 + r) * VD + q4 * 64);
    uint32_t base = aB + (uint32_t)(r * PGA) * 8u;
#pragma unroll
    for (int t = 0; t < 16; ++t) {
        float4 v = ok ? src[t] : make_float4(0.f, 0.f, 0.f, 0.f);
        int j0 = q4 * 32 + 2 * t;
        uint32_t h, l;
        split2(v.x, v.y, h, l);
        sts64(base + (uint32_t)(j0 ^ q4) * 8u, h, l);
        split2(v.z, v.w, h, l);
        sts64(base + (uint32_t)((j0 + 1) ^ q4) * 8u, h, l);
    }
}

// -------- trivial kernels --------
__global__ void k_zero(float* __restrict__ out, int n) {
    int i = blockIdx.x * blockDim.x + threadIdx.x;
    if (i < n) out[i] = 0.0f;
}
__global__ void k_offsets(const int* __restrict__ map) {
    int v = blockIdx.x * blockDim.x + threadIdx.x;
    if (v >= V_NODES) return;
    int m = map[v];
    int prev = (v == 0) ? -1 : map[v - 1];
    for (int g = prev + 1; g <= m; ++g) g_start_arr[g] = v;
    if (v == V_NODES - 1)
        for (int g = m + 1; g <= G_NUM; ++g) g_start_arr[g] = V_NODES;
}

// build frag-ordered hi/lo bf16 weight images
__global__ void k_prep(const float* __restrict__ sw1,
                       const float* __restrict__ tw1,
                       const float* __restrict__ tw2) {
    int i = blockIdx.x * blockDim.x + threadIdx.x;
    if (i >= 8192) return;
    int ks = i >> 9, n = (i >> 2) & 127, c = i & 3;
    int k0 = ks * 16 + 2 * c;
    uint4 e;
    split2(sw1[(size_t)k0 * HID + n], sw1[(size_t)(k0 + 1) * HID + n], e.x, e.y);
    split2(sw1[(size_t)(k0 + 8) * HID + n], sw1[(size_t)(k0 + 9) * HID + n], e.z, e.w);
    g_b1s[i] = e;
    split2(tw1[(size_t)k0 * HID + n], tw1[(size_t)(k0 + 1) * HID + n], e.x, e.y);
    split2(tw1[(size_t)(k0 + 8) * HID + n], tw1[(size_t)(k0 + 9) * HID + n], e.z, e.w);
    g_b1t[i] = e;
    int half = i >> 12, ks2 = (i >> 9) & 7;
    int ng = half * 128 + n, k2 = ks2 * 16 + 2 * c;
    split2(tw2[(size_t)k2 * GD + ng], tw2[(size_t)(k2 + 1) * GD + ng], e.x, e.y);
    split2(tw2[(size_t)(k2 + 8) * GD + ng], tw2[(size_t)(k2 + 9) * GD + ng], e.z, e.w);
    g_b2t[i] = e;
}

// -------- fused: scores + hidden_t --------
__global__ void __launch_bounds__(NT, 1) k_main(const float* __restrict__ E,
                                                const float* __restrict__ W2s) {
    extern __shared__ uint8_t smemraw[];
    uint32_t sb = smem_u32(smemraw);
    __shared__ float sW2[HID * 8];
    __shared__ float sScore[TM * 8];
    int tid = threadIdx.x;
    int m0 = blockIdx.x * TM;
    for (int i = tid; i < HID * 8; i += NT) sW2[i] = W2s[i];
    for (int i = tid; i < TM * 8; i += NT) sScore[i] = 0.f;

    stageE(E, m0, sb, tid);

    int lane = tid & 31, wid = tid >> 5, warpM = wid >> 2, warpN = wid & 3;
    int g = lane >> 2, cc = lane & 3;

    float acc[2][4][4];
#pragma unroll
    for (int a = 0; a < 2; ++a)
#pragma unroll
        for (int b = 0; b < 4; ++b)
#pragma unroll
            for (int q = 0; q < 4; ++q) acc[a][b][q] = 0.f;
    __syncthreads();

    // ---- GEMM 1: hidden_t = relu(E @ W1t) -> g_hidden (phase2 frag layout) ----
    gemm_direct<16, PGA, 1>(sb, g_b1t, acc, lane, warpM, warpN);
#pragma unroll
    for (int mt = 0; mt < 2; ++mt)
#pragma unroll
        for (int i2 = 0; i2 < 2; ++i2) {
            int v = m0 + warpM * 32 + mt * 16 + i2 * 8 + g;
            if (v < V_NODES) {
#pragma unroll
                for (int nt = 0; nt < 4; ++nt) {
                    int g2 = warpN * 16 + nt * 4 + cc;
                    float x0 = fmaxf(acc[mt][nt][2 * i2], 0.f);
                    float x1 = fmaxf(acc[mt][nt][2 * i2 + 1], 0.f);
                    uint2 hl;
                    split2(x0, x1, hl.x, hl.y);
                    g_hidden[(size_t)v * 64 + g2] = hl;
                }
            }
        }

    // ---- GEMM 2: scores = relu(E @ W1s) @ W2s ----
#pragma unroll
    for (int a = 0; a < 2; ++a)
#pragma unroll
        for (int b = 0; b < 4; ++b)
#pragma unroll
            for (int q = 0; q < 4; ++q) acc[a][b][q] = 0.f;
    gemm_direct<16, PGA, 1>(sb, g_b1s, acc, lane, warpM, warpN);

    float p[4][8];
#pragma unroll
    for (int r = 0; r < 4; ++r)
#pragma unroll
        for (int h = 0; h < 8; ++h) p[r][h] = 0.f;
#pragma unroll
    for (int mt = 0; mt < 2; ++mt)
#pragma unroll
        for (int nt = 0; nt < 4; ++nt) {
            int c0 = warpN * 32 + nt * 8 + cc * 2;
            float v0 = fmaxf(acc[mt][nt][0], 0.f), v1 = fmaxf(acc[mt][nt][1], 0.f);
            float v2 = fmaxf(acc[mt][nt][2], 0.f), v3 = fmaxf(acc[mt][nt][3], 0.f);
#pragma unroll
            for (int h = 0; h < 8; ++h) {
                p[mt * 2 + 0][h] += v0 * sW2[c0 * 8 + h] + v1 * sW2[c0 * 8 + 8 + h];
                p[mt * 2 + 1][h] += v2 * sW2[c0 * 8 + h] + v3 * sW2[c0 * 8 + 8 + h];
            }
        }
#pragma unroll
    for (int off = 1; off <= 2; off <<= 1)
#pragma unroll
        for (int r = 0; r < 4; ++r)
#pragma unroll
            for (int h = 0; h < 8; ++h)
                p[r][h] += __shfl_xor_sync(0xFFFFFFFFu, p[r][h], off);
    if (cc == 0) {
#pragma unroll
        for (int mt = 0; mt < 2; ++mt)
#pragma unroll
            for (int i2 = 0; i2 < 2; ++i2) {
                int row = warpM * 32 + mt * 16 + i2 * 8 + g;
#pragma unroll
                for (int h = 0; h < 8; ++h)
                    atomicAdd(&sScore[row * 8 + h], p[mt * 2 + i2][h]);
            }
    }
    __syncthreads();
    for (int i = tid; i < TM * 8; i += NT) {
        int v = m0 + (i >> 3);
        if (v < V_NODES) g_scores[(size_t)v * 8 + (i & 7)] = sScore[i];
    }
}

// -------- per-graph softmax stats --------
__global__ void __launch_bounds__(128) k_segstats() {
    int g = blockIdx.x;
    int s = g_start_arr[g], e = g_start_arr[g + 1];
    __shared__ float red[128];
    __shared__ float sm8[8];
    int tid = threadIdx.x, h = tid & 7, k = tid >> 3;

    float mx = -INFINITY;
    for (int v = s + k; v < e; v += 16) mx = fmaxf(mx, g_scores[(size_t)v * 8 + h]);
    red[tid] = mx;
    __syncthreads();
    for (int st = 64; st >= 8; st >>= 1) {
        if (tid < st) red[tid] = fmaxf(red[tid], red[tid + st]);
        __syncthreads();
    }
    if (tid < 8) {
        float m = red[tid];
        if (!isfinite(m)) m = 0.0f;
        sm8[tid] = m;
        g_m[g * 8 + tid] = m;
    }
    __syncthreads();
    float m = sm8[h];
    float sum = 0.f;
    for (int v = s + k; v < e; v += 16) sum += expf(g_scores[(size_t)v * 8 + h] - m);
    red[tid] = sum;
    __syncthreads();
    for (int st = 64; st >= 8; st >>= 1) {
        if (tid < st) red[tid] += red[tid + st];
        __syncthreads();
    }
    if (tid < 8) g_d[g * 8 + tid] = red[tid];
}

// -------- phase2: out += segsum( softmax_w * relu(hidden @ W2t) ) --------
__global__ void __launch_bounds__(NT, 1) k_transform2(const int* __restrict__ map,
                                                      float* __restrict__ out) {
    extern __shared__ uint8_t smemraw[];
    uint32_t sb = smem_u32(smemraw);
    float* sR = (float*)(smemraw + OFF_SR2);
    __shared__ float swgt[TM * 8];
    __shared__ int smap[TM];
    __shared__ int segStart[TM + 1];
    __shared__ int segGraph[TM];
    __shared__ int nseg;

    int tid = threadIdx.x;
    int m0 = blockIdx.x * TM;

    // async-load hidden tile into A2 (pitch PGA2, natural layout)
    for (int i = tid; i < 4096; i += NT) {
        int row = i >> 5, ch = i & 31;
        int v = m0 + row;
        if (v > V_NODES - 1) v = V_NODES - 1;   // clamp; rows past end never read
        cpa16(sb + (uint32_t)(row * PGA2 + ch * 2) * 8u,
              &g_hidden[(size_t)v * 64 + ch * 2]);
    }
    CP_COMMIT();

    for (int o = tid; o < TM * 8; o += NT) {
        int row = o >> 3, h = o & 7;
        int v = m0 + row;
        float w = 0.f;
        if (v < V_NODES) {
            int gg = map[v];
            if (h == 0) smap[row] = gg;
            float D = g_d[gg * 8 + h];
            if (D > 0.f)
                w = expf(g_scores[(size_t)v * 8 + h] - g_m[gg * 8 + h]) / D;
        } else if (h == 0) {
            smap[row] = -1;
        }
        swgt[o] = w;
    }
    __syncthreads();
    if (tid == 0) {
        int ns = 0, prev = -2, endr = TM;
        for (int r = 0; r < TM; ++r) {
            int mg = smap[r];
            if (mg < 0) { endr = r; break; }
            if (mg != prev) { segStart[ns] = r; segGraph[ns] = mg; prev = mg; ++ns; }
        }
        segStart[ns] = endr;
        nseg = ns;
    }
    CP_WAIT0();
    __syncthreads();

    int lane = tid & 31, wid = tid >> 5, warpM = wid >> 2, warpN = wid & 3;
    int g = lane >> 2, cc = lane & 3;

    float acc[2][4][4];
#pragma unroll
    for (int half = 0; half < 2; ++half) {
#pragma unroll
        for (int a = 0; a < 2; ++a)
#pragma unroll
            for (int b = 0; b < 4; ++b)
#pragma unroll
                for (int q = 0; q < 4; ++q) acc[a][b][q] = 0.f;

        gemm_direct<8, PGA2, 0>(sb, g_b2t + half * 4096, acc, lane, warpM, warpN);

        // relu * softmax-weight -> sR
#pragma unroll
        for (int mt = 0; mt < 2; ++mt)
#pragma unroll
            for (int i2 = 0; i2 < 2; ++i2) {
                int row = warpM * 32 + mt * 16 + i2 * 8 + g;
                float w = swgt[row * 8 + half * 4 + warpN];
#pragma unroll
                for (int nt = 0; nt < 4; ++nt) {
                    int col = warpN * 32 + nt * 8 + cc * 2;
                    sR[row * 132 + col]     = fmaxf(acc[mt][nt][2 * i2], 0.f) * w;
                    sR[row * 132 + col + 1] = fmaxf(acc[mt][nt][2 * i2 + 1], 0.f) * w;
                }
            }
        __syncthreads();

        // segment-reduce rows, one atomic per (segment, col)
        {
            int col = tid & 127, slot = tid >> 7;
            for (int sg = slot; sg < nseg; sg += 4) {
                int r0 = segStart[sg], r1 = segStart[sg + 1];
                float s = 0.f;
                for (int r = r0; r < r1; ++r) s += sR[r * 132 + col];
                atomicAdd(&out[(size_t)segGraph[sg] * GD + half * 128 + col], s);
            }
        }
        __syncthreads();
    }
}

// -------- launch --------
extern "C" void kernel_launch(void* const* d_in, const int* in_sizes, int n_in,
                              void* d_out, int out_size) {
    const float* E   = (const float*)d_in[0];
    const int*   map = (const int*)d_in[1];
    int base = (in_sizes[2] == 1) ? 3 : 2;
    const float* sw1 = (const float*)d_in[base + 0];
    const float* sw2 = (const float*)d_in[base + 1];
    const float* tw1 = (const float*)d_in[base + 2];
    const float* tw2 = (const float*)d_in[base + 3];
    float* out = (float*)d_out;

    cudaFuncSetAttribute(k_main, cudaFuncAttributeMaxDynamicSharedMemorySize,
                         SMEM_MAIN);
    cudaFuncSetAttribute(k_transform2, cudaFuncAttributeMaxDynamicSharedMemorySize,
                         SMEM_TRANS2);

    int nOut = G_NUM * GD;
    int nTiles = (V_NODES + TM - 1) / TM;

    k_zero<<<(nOut + 255) / 256, 256>>>(out, nOut);
    k_offsets<<<(V_NODES + 255) / 256, 256>>>(map);
    k_prep<<<32, 256>>>(sw1, tw1, tw2);
    k_main<<<nTiles, NT, SMEM_MAIN>>>(E, sw2);
    k_segstats<<<G_NUM, 128>>>();
    k_transform2<<<nTiles, NT, SMEM_TRANS2>>>(map, out);
}